// round 1
// baseline (speedup 1.0000x reference)
#include <cuda_runtime.h>
#include <cuda_bf16.h>
#include <math.h>

// Problem constants (fixed shapes for GAT_76184129896720)
#define NN 30000
#define NPAD 30080           // 235 * 128, padded for GEMM
#define EE 480000
#define EMB 256
#define GG 512
#define NEG_SLOPE 0.2f

// ---------------- device scratch (static; no allocations allowed) ----------
__device__ float g_h[NPAD * EMB];     // node features (updated per layer)
__device__ float g_xl[NPAD * EMB];    // h @ W[l]
__device__ float g_as[NN];
__device__ float g_ad[NN];
__device__ float g_alpha[EE];         // per-CSR-slot alpha, then exp weights
__device__ float g_edot[EE];          // e_enc . (We @ a_e) per edge
__device__ float g_wself[NN];
__device__ float g_denom[NN];
__device__ int   g_deg[NN];
__device__ int   g_rowptr[NN + 1];
__device__ int   g_cursor[NN];
__device__ int   g_csr_src[EE];
__device__ int   g_csr_eid[EE];
__device__ float g_dtable[48];        // 3 x 16 bond scalar LUT (per layer)
__device__ float g_wv[EMB];           // W1 @ W2
__device__ float g_bconst;            // b1 @ W2 + b2
__device__ float g_gsum[GG];
__device__ float g_gcnt[GG];

// ---------------- helpers ---------------------------------------------------
__device__ __forceinline__ float warp_sum(float v) {
#pragma unroll
    for (int o = 16; o > 0; o >>= 1) v += __shfl_xor_sync(0xffffffffu, v, o);
    return v;
}
__device__ __forceinline__ float warp_max(float v) {
#pragma unroll
    for (int o = 16; o > 0; o >>= 1) v = fmaxf(v, __shfl_xor_sync(0xffffffffu, v, o));
    return v;
}

// ---------------- kernels ---------------------------------------------------

// zero counters + padding rows of h
__global__ void k_init() {
    int i = blockIdx.x * blockDim.x + threadIdx.x;
    if (i < NN) { g_deg[i] = 0; g_cursor[i] = 0; }
    if (i < GG) { g_gsum[i] = 0.f; g_gcnt[i] = 0.f; }
    if (i < (NPAD - NN) * EMB) g_h[NN * EMB + i] = 0.f;
}

// AtomEncoder: h[n][c] = sum_i atom_emb[i][x[n,i]][c]
__global__ void k_atom(const int* __restrict__ x, const float* __restrict__ emb) {
    int n = blockIdx.x;
    int c = threadIdx.x;  // 256
    __shared__ int xi[9];
    if (c < 9) xi[c] = x[n * 9 + c];
    __syncthreads();
    float s = 0.f;
#pragma unroll
    for (int i = 0; i < 9; i++) s += emb[(i * 128 + xi[i]) * EMB + c];
    g_h[n * EMB + c] = s;
}

__global__ void k_hist(const int* __restrict__ dst) {
    int e = blockIdx.x * blockDim.x + threadIdx.x;
    if (e < EE) atomicAdd(&g_deg[dst[e]], 1);
}

// exclusive prefix sum over g_deg -> g_rowptr (single block)
__global__ void k_scan() {
    __shared__ int sh[1024];
    int tid = threadIdx.x;
    int offset = 0;
    for (int base = 0; base < NN; base += 1024) {
        int i = base + tid;
        int v = (i < NN) ? g_deg[i] : 0;
        sh[tid] = v;
        __syncthreads();
#pragma unroll
        for (int d = 1; d < 1024; d <<= 1) {
            int t = (tid >= d) ? sh[tid - d] : 0;
            __syncthreads();
            sh[tid] += t;
            __syncthreads();
        }
        if (i < NN) g_rowptr[i + 1] = offset + sh[tid];
        offset += sh[1023];
        __syncthreads();
    }
    if (tid == 0) g_rowptr[0] = 0;
}

__global__ void k_scatter(const int* __restrict__ src, const int* __restrict__ dst) {
    int e = blockIdx.x * blockDim.x + threadIdx.x;
    if (e >= EE) return;
    int d = dst[e];
    int pos = g_rowptr[d] + atomicAdd(&g_cursor[d], 1);
    g_csr_src[pos] = src[e];
    g_csr_eid[pos] = e;
}

// head precompute: wv = W1 @ W2, bconst = b1 @ W2 + b2
__global__ void k_head(const float* __restrict__ W1, const float* __restrict__ b1,
                       const float* __restrict__ W2, const float* __restrict__ b2) {
    int c = threadIdx.x;  // 256
    float acc = 0.f;
#pragma unroll 8
    for (int j = 0; j < EMB; j++) acc += W1[c * EMB + j] * W2[j];
    g_wv[c] = acc;
    __shared__ float sh[EMB];
    sh[c] = b1[c] * W2[c];
    __syncthreads();
    for (int s = 128; s > 0; s >>= 1) {
        if (c < s) sh[c] += sh[c + s];
        __syncthreads();
    }
    if (c == 0) g_bconst = sh[0] + b2[0];
}

// per-layer: wa = We[l] @ att_edge[l]  (3-vec), then LUT[j][v] = bond_emb[l,j,v,:].wa
__global__ void k_lprep(const float* __restrict__ We, const float* __restrict__ att_edge,
                        const float* __restrict__ bond_emb, int l) {
    __shared__ float wa[3];
    int t = threadIdx.x;  // 96
    int w = t >> 5, lane = t & 31;
    float p = 0.f;
    for (int k = lane; k < EMB; k += 32)
        p += We[(l * 3 + w) * EMB + k] * att_edge[l * EMB + k];
    p = warp_sum(p);
    if (lane == 0) wa[w] = p;
    __syncthreads();
    if (t < 48) {
        int j = t >> 4, v = t & 15;
        const float* be = bond_emb + ((size_t)(l * 3 + j) * 16 + v) * 3;
        g_dtable[t] = be[0] * wa[0] + be[1] * wa[1] + be[2] * wa[2];
    }
}

__global__ void k_edot(const int* __restrict__ ea) {
    int e = blockIdx.x * blockDim.x + threadIdx.x;
    if (e >= EE) return;
    int a0 = ea[e * 3 + 0], a1 = ea[e * 3 + 1], a2 = ea[e * 3 + 2];
    g_edot[e] = g_dtable[a0] + g_dtable[16 + a1] + g_dtable[32 + a2];
}

// SGEMM: g_xl = g_h @ B  (NPAD x 256 x 256), 128x128x16 tiles, 8x8 per thread
__global__ __launch_bounds__(256, 2) void k_sgemm(const float* __restrict__ B) {
    __shared__ float As[16][132];
    __shared__ float Bs[16][128];
    const int tid = threadIdx.x;
    const int r0 = blockIdx.x * 128;
    const int c0 = blockIdx.y * 128;
    const int tr = (tid >> 4) << 3;
    const int tc = (tid & 15) << 3;
    const int arow = tid >> 2;
    const int ak = (tid & 3) << 2;
    const int brow = tid >> 5;
    const int bc = (tid & 31) << 2;

    float acc[8][8];
#pragma unroll
    for (int i = 0; i < 8; i++)
#pragma unroll
        for (int j = 0; j < 8; j++) acc[i][j] = 0.f;

    const float* Abase = g_h + (size_t)(r0 + arow) * EMB + ak;
    const float* Bbase = B + (size_t)brow * EMB + c0 + bc;

    for (int k0 = 0; k0 < 256; k0 += 16) {
        float4 va0 = *(const float4*)(Abase + k0);
        float4 va1 = *(const float4*)(Abase + 64 * EMB + k0);
        float4 vb0 = *(const float4*)(Bbase + (size_t)k0 * EMB);
        float4 vb1 = *(const float4*)(Bbase + (size_t)(k0 + 8) * EMB);
        As[ak + 0][arow] = va0.x; As[ak + 1][arow] = va0.y;
        As[ak + 2][arow] = va0.z; As[ak + 3][arow] = va0.w;
        As[ak + 0][arow + 64] = va1.x; As[ak + 1][arow + 64] = va1.y;
        As[ak + 2][arow + 64] = va1.z; As[ak + 3][arow + 64] = va1.w;
        *(float4*)&Bs[brow][bc] = vb0;
        *(float4*)&Bs[brow + 8][bc] = vb1;
        __syncthreads();
#pragma unroll
        for (int k = 0; k < 16; k++) {
            float4 a0 = *(const float4*)&As[k][tr];
            float4 a1 = *(const float4*)&As[k][tr + 4];
            float4 b0 = *(const float4*)&Bs[k][tc];
            float4 b1 = *(const float4*)&Bs[k][tc + 4];
            float a[8] = {a0.x, a0.y, a0.z, a0.w, a1.x, a1.y, a1.z, a1.w};
            float b[8] = {b0.x, b0.y, b0.z, b0.w, b1.x, b1.y, b1.z, b1.w};
#pragma unroll
            for (int i = 0; i < 8; i++)
#pragma unroll
                for (int j = 0; j < 8; j++)
                    acc[i][j] = fmaf(a[i], b[j], acc[i][j]);
        }
        __syncthreads();
    }
    float* Crow = g_xl + (size_t)(r0 + tr) * EMB + c0 + tc;
#pragma unroll
    for (int i = 0; i < 8; i++) {
        *(float4*)(Crow + i * EMB) = make_float4(acc[i][0], acc[i][1], acc[i][2], acc[i][3]);
        *(float4*)(Crow + i * EMB + 4) = make_float4(acc[i][4], acc[i][5], acc[i][6], acc[i][7]);
    }
}

// as[n] = xl[n].att_src ; ad[n] = xl[n].att_dst   (warp per node)
__global__ void k_asad(const float* __restrict__ att_s, const float* __restrict__ att_d) {
    int gw = (blockIdx.x * blockDim.x + threadIdx.x) >> 5;
    int lane = threadIdx.x & 31;
    if (gw >= NN) return;
    const float4* row = (const float4*)(g_xl + (size_t)gw * EMB);
    const float4* s4 = (const float4*)att_s;
    const float4* d4 = (const float4*)att_d;
    float4 v0 = row[lane], v1 = row[lane + 32];
    float4 s0 = s4[lane], s1 = s4[lane + 32];
    float4 dd0 = d4[lane], dd1 = d4[lane + 32];
    float ss = v0.x * s0.x + v0.y * s0.y + v0.z * s0.z + v0.w * s0.w +
               v1.x * s1.x + v1.y * s1.y + v1.z * s1.z + v1.w * s1.w;
    float dd = v0.x * dd0.x + v0.y * dd0.y + v0.z * dd0.z + v0.w * dd0.w +
               v1.x * dd1.x + v1.y * dd1.y + v1.z * dd1.z + v1.w * dd1.w;
    ss = warp_sum(ss);
    dd = warp_sum(dd);
    if (lane == 0) { g_as[gw] = ss; g_ad[gw] = dd; }
}

// per-node (warp): alpha + leaky + softmax (max/denom), includes self-loop
__global__ void k_alpha() {
    int gw = (blockIdx.x * blockDim.x + threadIdx.x) >> 5;
    int lane = threadIdx.x & 31;
    if (gw >= NN) return;
    int start = g_rowptr[gw], end = g_rowptr[gw + 1];
    float adn = g_ad[gw];
    float mx = -1e30f, esum = 0.f;
    for (int pos = start + lane; pos < end; pos += 32) {
        float ed = g_edot[g_csr_eid[pos]];
        float a = g_as[g_csr_src[pos]] + adn + ed;
        a = (a >= 0.f) ? a : NEG_SLOPE * a;
        g_alpha[pos] = a;
        mx = fmaxf(mx, a);
        esum += ed;
    }
    mx = warp_max(mx);
    esum = warp_sum(esum);
    int deg = end - start;
    float selfa = g_as[gw] + adn + esum / fmaxf((float)deg, 1.0f);
    selfa = (selfa >= 0.f) ? selfa : NEG_SLOPE * selfa;
    float m = fmaxf(mx, selfa);
    float dsum = 0.f;
    for (int pos = start + lane; pos < end; pos += 32) {
        float p = expf(g_alpha[pos] - m);
        g_alpha[pos] = p;
        dsum += p;
    }
    dsum = warp_sum(dsum);
    if (lane == 0) {
        float ws = expf(selfa - m);
        g_wself[gw] = ws;
        g_denom[gw] = dsum + ws;
    }
}

// per-node (warp): out = (sum w*xl[src] + wself*xl[n]) / denom + bias; relu; += h
__global__ void k_aggr(const float* __restrict__ bias, int do_relu) {
    int gw = (blockIdx.x * blockDim.x + threadIdx.x) >> 5;
    int lane = threadIdx.x & 31;
    if (gw >= NN) return;
    int start = g_rowptr[gw], end = g_rowptr[gw + 1];
    float4 acc0 = make_float4(0, 0, 0, 0), acc1 = make_float4(0, 0, 0, 0);
    for (int pos = start; pos < end; pos++) {
        float w = g_alpha[pos];
        int s = g_csr_src[pos];
        const float4* row = (const float4*)(g_xl + (size_t)s * EMB);
        float4 v0 = row[lane], v1 = row[lane + 32];
        acc0.x += w * v0.x; acc0.y += w * v0.y; acc0.z += w * v0.z; acc0.w += w * v0.w;
        acc1.x += w * v1.x; acc1.y += w * v1.y; acc1.z += w * v1.z; acc1.w += w * v1.w;
    }
    {
        float w = g_wself[gw];
        const float4* row = (const float4*)(g_xl + (size_t)gw * EMB);
        float4 v0 = row[lane], v1 = row[lane + 32];
        acc0.x += w * v0.x; acc0.y += w * v0.y; acc0.z += w * v0.z; acc0.w += w * v0.w;
        acc1.x += w * v1.x; acc1.y += w * v1.y; acc1.z += w * v1.z; acc1.w += w * v1.w;
    }
    float inv = 1.0f / g_denom[gw];
    const float4* b4 = (const float4*)bias;
    float4 b0 = b4[lane], b1 = b4[lane + 32];
    float4* hrow = (float4*)(g_h + (size_t)gw * EMB);
    float4 h0 = hrow[lane], h1 = hrow[lane + 32];
    float4 r0, r1;
    r0.x = acc0.x * inv + b0.x; r0.y = acc0.y * inv + b0.y;
    r0.z = acc0.z * inv + b0.z; r0.w = acc0.w * inv + b0.w;
    r1.x = acc1.x * inv + b1.x; r1.y = acc1.y * inv + b1.y;
    r1.z = acc1.z * inv + b1.z; r1.w = acc1.w * inv + b1.w;
    if (do_relu) {
        r0.x = fmaxf(r0.x, 0.f); r0.y = fmaxf(r0.y, 0.f);
        r0.z = fmaxf(r0.z, 0.f); r0.w = fmaxf(r0.w, 0.f);
        r1.x = fmaxf(r1.x, 0.f); r1.y = fmaxf(r1.y, 0.f);
        r1.z = fmaxf(r1.z, 0.f); r1.w = fmaxf(r1.w, 0.f);
    }
    r0.x += h0.x; r0.y += h0.y; r0.z += h0.z; r0.w += h0.w;
    r1.x += h1.x; r1.y += h1.y; r1.z += h1.z; r1.w += h1.w;
    hrow[lane] = r0;
    hrow[lane + 32] = r1;
}

// pooling: s[n] = h[n].wv, atomic into graph buckets
__global__ void k_pool(const int* __restrict__ batch) {
    int gw = (blockIdx.x * blockDim.x + threadIdx.x) >> 5;
    int lane = threadIdx.x & 31;
    if (gw >= NN) return;
    const float4* row = (const float4*)(g_h + (size_t)gw * EMB);
    const float4* w4 = (const float4*)g_wv;
    float4 v0 = row[lane], v1 = row[lane + 32];
    float4 w0 = w4[lane], w1 = w4[lane + 32];
    float s = v0.x * w0.x + v0.y * w0.y + v0.z * w0.z + v0.w * w0.w +
              v1.x * w1.x + v1.y * w1.y + v1.z * w1.z + v1.w * w1.w;
    s = warp_sum(s);
    if (lane == 0) {
        int g = batch[gw];
        atomicAdd(&g_gsum[g], s);
        atomicAdd(&g_gcnt[g], 1.0f);
    }
}

__global__ void k_final(float* __restrict__ out) {
    int g = blockIdx.x * blockDim.x + threadIdx.x;
    if (g < GG) out[g] = g_gsum[g] / fmaxf(g_gcnt[g], 1.0f) + g_bconst;
}

// ---------------- launch -----------------------------------------------------
extern "C" void kernel_launch(void* const* d_in, const int* in_sizes, int n_in,
                              void* d_out, int out_size) {
    const int* x = (const int*)d_in[0];
    const int* edge_index = (const int*)d_in[1];
    const int* edge_attr = (const int*)d_in[2];
    const int* batch = (const int*)d_in[3];
    const float* atom_emb = (const float*)d_in[4];
    const float* bond_emb = (const float*)d_in[5];
    const float* W = (const float*)d_in[6];
    const float* att_src = (const float*)d_in[7];
    const float* att_dst = (const float*)d_in[8];
    const float* We = (const float*)d_in[9];
    const float* att_edge = (const float*)d_in[10];
    const float* bias = (const float*)d_in[11];
    const float* W1 = (const float*)d_in[12];
    const float* b1 = (const float*)d_in[13];
    const float* W2 = (const float*)d_in[14];
    const float* b2 = (const float*)d_in[15];
    float* out = (float*)d_out;

    const int* src = edge_index;
    const int* dst = edge_index + EE;

    const int eblocks = (EE + 255) / 256;
    const int nwarp_blocks = (NN + 7) / 8;  // 8 warps per 256-thread block

    k_init<<<(NPAD * EMB / 256 + 1), 256>>>();  // covers all zeroed ranges via bounds checks
    k_atom<<<NN, 256>>>(x, atom_emb);
    k_hist<<<eblocks, 256>>>(dst);
    k_scan<<<1, 1024>>>();
    k_scatter<<<eblocks, 256>>>(src, dst);
    k_head<<<1, 256>>>(W1, b1, W2, b2);

    for (int l = 0; l < 3; l++) {
        k_lprep<<<1, 96>>>(We, att_edge, bond_emb, l);
        k_edot<<<eblocks, 256>>>(edge_attr);
        k_sgemm<<<dim3(NPAD / 128, EMB / 128), 256>>>(W + (size_t)l * EMB * EMB);
        k_asad<<<nwarp_blocks, 256>>>(att_src + l * EMB, att_dst + l * EMB);
        k_alpha<<<nwarp_blocks, 256>>>();
        k_aggr<<<nwarp_blocks, 256>>>(bias + l * EMB, (l < 2) ? 1 : 0);
    }

    k_pool<<<nwarp_blocks, 256>>>(batch);
    k_final<<<2, 256>>>(out);
}

// round 2
// speedup vs baseline: 1.3724x; 1.3724x over previous
#include <cuda_runtime.h>
#include <cuda_bf16.h>
#include <math.h>

// Problem constants (fixed shapes for GAT_76184129896720)
#define NN 30000
#define NPAD 30080           // 235 * 128, padded for GEMM
#define EE 480000
#define EMB 256
#define GG 512
#define NEG_SLOPE 0.2f

// ---------------- device scratch (static; no allocations allowed) ----------
__device__ float g_h[NPAD * EMB];     // node features (updated per layer)
__device__ float g_xl[NPAD * EMB];    // h @ W[l]
__device__ float g_as[NN];
__device__ float g_ad[NN];
__device__ float g_alpha[EE];         // per-CSR-slot alpha, then exp weights
__device__ float g_edot[EE];          // e_enc . (We @ a_e) per edge
__device__ float g_wself[NN];
__device__ float g_denom[NN];
__device__ int   g_deg[NN];
__device__ int   g_rowptr[NN + 1];
__device__ int   g_cursor[NN];
__device__ int   g_csr_src[EE];
__device__ int   g_csr_eid[EE];
__device__ float g_dtable[48];        // 3 x 16 bond scalar LUT (per layer)
__device__ float g_wv[EMB];           // W1 @ W2
__device__ float g_bconst;            // b1 @ W2 + b2
__device__ float g_gsum[GG];
__device__ float g_gcnt[GG];

// ---------------- helpers ---------------------------------------------------
__device__ __forceinline__ float warp_sum(float v) {
#pragma unroll
    for (int o = 16; o > 0; o >>= 1) v += __shfl_xor_sync(0xffffffffu, v, o);
    return v;
}
__device__ __forceinline__ float warp_max(float v) {
#pragma unroll
    for (int o = 16; o > 0; o >>= 1) v = fmaxf(v, __shfl_xor_sync(0xffffffffu, v, o));
    return v;
}
__device__ __forceinline__ unsigned f2tf(float f) {
    unsigned u;
    asm("cvt.rna.tf32.f32 %0, %1;" : "=r"(u) : "f"(f));
    return u;
}

// ---------------- kernels ---------------------------------------------------

// zero counters + padding rows of h
__global__ void k_init() {
    int i = blockIdx.x * blockDim.x + threadIdx.x;
    if (i < NN) { g_deg[i] = 0; g_cursor[i] = 0; }
    if (i < GG) { g_gsum[i] = 0.f; g_gcnt[i] = 0.f; }
    if (i < (NPAD - NN) * EMB) g_h[NN * EMB + i] = 0.f;
}

// AtomEncoder: h[n][c] = sum_i atom_emb[i][x[n,i]][c]
__global__ void k_atom(const int* __restrict__ x, const float* __restrict__ emb) {
    int n = blockIdx.x;
    int c = threadIdx.x;  // 256
    __shared__ int xi[9];
    if (c < 9) xi[c] = x[n * 9 + c];
    __syncthreads();
    float s = 0.f;
#pragma unroll
    for (int i = 0; i < 9; i++) s += emb[(i * 128 + xi[i]) * EMB + c];
    g_h[n * EMB + c] = s;
}

__global__ void k_hist(const int* __restrict__ dst) {
    int e = blockIdx.x * blockDim.x + threadIdx.x;
    if (e < EE) atomicAdd(&g_deg[dst[e]], 1);
}

// fast single-block scan: 1024 threads x 30 serial elems + shuffle block scan
#define SCAN_PER 30
__global__ void k_scan() {
    __shared__ int warpsum[32];
    int tid = threadIdx.x;
    int lane = tid & 31, wid = tid >> 5;
    int base = tid * SCAN_PER;
    int v[SCAN_PER];
    int tot = 0;
#pragma unroll
    for (int i = 0; i < SCAN_PER; i++) {
        int idx = base + i;
        v[i] = (idx < NN) ? g_deg[idx] : 0;
        tot += v[i];
    }
    // inclusive warp scan of per-thread totals
    int x = tot;
#pragma unroll
    for (int o = 1; o < 32; o <<= 1) {
        int y = __shfl_up_sync(0xffffffffu, x, o);
        if (lane >= o) x += y;
    }
    if (lane == 31) warpsum[wid] = x;
    __syncthreads();
    if (wid == 0) {
        int w = warpsum[lane];
#pragma unroll
        for (int o = 1; o < 32; o <<= 1) {
            int y = __shfl_up_sync(0xffffffffu, w, o);
            if (lane >= o) w += y;
        }
        warpsum[lane] = w;
    }
    __syncthreads();
    int excl = x - tot + ((wid > 0) ? warpsum[wid - 1] : 0);
    int run = excl;
#pragma unroll
    for (int i = 0; i < SCAN_PER; i++) {
        int idx = base + i;
        if (idx < NN) {
            run += v[i];
            g_rowptr[idx + 1] = run;
        }
    }
    if (tid == 0) g_rowptr[0] = 0;
}

__global__ void k_scatter(const int* __restrict__ src, const int* __restrict__ dst) {
    int e = blockIdx.x * blockDim.x + threadIdx.x;
    if (e >= EE) return;
    int d = dst[e];
    int pos = g_rowptr[d] + atomicAdd(&g_cursor[d], 1);
    g_csr_src[pos] = src[e];
    g_csr_eid[pos] = e;
}

// head precompute: wv = W1 @ W2, bconst = b1 @ W2 + b2
__global__ void k_head(const float* __restrict__ W1, const float* __restrict__ b1,
                       const float* __restrict__ W2, const float* __restrict__ b2) {
    int c = threadIdx.x;  // 256
    float acc = 0.f;
#pragma unroll 8
    for (int j = 0; j < EMB; j++) acc += W1[c * EMB + j] * W2[j];
    g_wv[c] = acc;
    __shared__ float sh[EMB];
    sh[c] = b1[c] * W2[c];
    __syncthreads();
    for (int s = 128; s > 0; s >>= 1) {
        if (c < s) sh[c] += sh[c + s];
        __syncthreads();
    }
    if (c == 0) g_bconst = sh[0] + b2[0];
}

// per-layer: wa = We[l] @ att_edge[l]  (3-vec), then LUT[j][v] = bond_emb[l,j,v,:].wa
__global__ void k_lprep(const float* __restrict__ We, const float* __restrict__ att_edge,
                        const float* __restrict__ bond_emb, int l) {
    __shared__ float wa[3];
    int t = threadIdx.x;  // 96
    int w = t >> 5, lane = t & 31;
    float p = 0.f;
    for (int k = lane; k < EMB; k += 32)
        p += We[(l * 3 + w) * EMB + k] * att_edge[l * EMB + k];
    p = warp_sum(p);
    if (lane == 0) wa[w] = p;
    __syncthreads();
    if (t < 48) {
        int j = t >> 4, v = t & 15;
        const float* be = bond_emb + ((size_t)(l * 3 + j) * 16 + v) * 3;
        g_dtable[t] = be[0] * wa[0] + be[1] * wa[1] + be[2] * wa[2];
    }
}

__global__ void k_edot(const int* __restrict__ ea) {
    int e = blockIdx.x * blockDim.x + threadIdx.x;
    if (e >= EE) return;
    int a0 = ea[e * 3 + 0], a1 = ea[e * 3 + 1], a2 = ea[e * 3 + 2];
    g_edot[e] = g_dtable[a0] + g_dtable[16 + a1] + g_dtable[32 + a2];
}

// ---------------- tf32 tensor-core GEMM: g_xl = g_h @ B ---------------------
// Block tile 128x128, K-slab 32, 8 warps (2x4), warp tile 64x32.
// mma.sync.aligned.m16n8k8.row.col.f32.tf32.tf32.f32
__global__ __launch_bounds__(256) void k_mma(const float* __restrict__ B) {
    __shared__ unsigned As[32][136];  // [k][m], stride 136 -> conflict-free frags
    __shared__ unsigned Bs[32][136];  // [k][n]
    const int tid = threadIdx.x;
    const int lane = tid & 31;
    const int w = tid >> 5;
    const int tig = lane & 3, gid = lane >> 2;
    const int warp_m = w >> 2;   // 0..1
    const int warp_n = w & 3;    // 0..3
    const int r0 = blockIdx.x * 128;
    const int c0 = blockIdx.y * 128;

    // global load mapping
    const int am = tid & 127;          // A row within tile
    const int ak0 = (tid >> 7) * 16;   // 0 or 16; thread covers k = ak0 + 4*i
    const int bn = (tid & 31) * 4;     // B col (float4)
    const int bk0 = tid >> 5;          // 0..7; thread covers k = bk0 + 8*p

    float acc[16][4];
#pragma unroll
    for (int i = 0; i < 16; i++)
#pragma unroll
        for (int j = 0; j < 4; j++) acc[i][j] = 0.f;

    const float* Ag = g_h + (size_t)(r0 + am) * EMB;
    const float* Bg = B + c0 + bn;

    float4 pa[4], pb[4];
#pragma unroll
    for (int i = 0; i < 4; i++) pa[i] = *(const float4*)(Ag + ak0 + 4 * i);
#pragma unroll
    for (int p = 0; p < 4; p++) pb[p] = *(const float4*)(Bg + (size_t)(bk0 + 8 * p) * EMB);

    for (int s = 0; s < 8; s++) {
        // store prefetched slab to smem (with tf32 rounding)
#pragma unroll
        for (int i = 0; i < 4; i++) {
            int k = ak0 + 4 * i;
            As[k + 0][am] = f2tf(pa[i].x);
            As[k + 1][am] = f2tf(pa[i].y);
            As[k + 2][am] = f2tf(pa[i].z);
            As[k + 3][am] = f2tf(pa[i].w);
        }
#pragma unroll
        for (int p = 0; p < 4; p++) {
            int k = bk0 + 8 * p;
            unsigned b0 = f2tf(pb[p].x), b1 = f2tf(pb[p].y);
            unsigned b2 = f2tf(pb[p].z), b3 = f2tf(pb[p].w);
            *(uint4*)&Bs[k][bn] = make_uint4(b0, b1, b2, b3);
        }
        __syncthreads();
        if (s < 7) {
            int k0 = (s + 1) * 32;
#pragma unroll
            for (int i = 0; i < 4; i++) pa[i] = *(const float4*)(Ag + k0 + ak0 + 4 * i);
#pragma unroll
            for (int p = 0; p < 4; p++)
                pb[p] = *(const float4*)(Bg + (size_t)(k0 + bk0 + 8 * p) * EMB);
        }
#pragma unroll
        for (int kk = 0; kk < 32; kk += 8) {
            unsigned af[4][4], bf[4][2];
#pragma unroll
            for (int mt = 0; mt < 4; mt++) {
                int m = warp_m * 64 + mt * 16 + gid;
                af[mt][0] = As[kk + tig][m];
                af[mt][1] = As[kk + tig][m + 8];
                af[mt][2] = As[kk + tig + 4][m];
                af[mt][3] = As[kk + tig + 4][m + 8];
            }
#pragma unroll
            for (int nt = 0; nt < 4; nt++) {
                int n = warp_n * 32 + nt * 8 + gid;
                bf[nt][0] = Bs[kk + tig][n];
                bf[nt][1] = Bs[kk + tig + 4][n];
            }
#pragma unroll
            for (int mt = 0; mt < 4; mt++)
#pragma unroll
                for (int nt = 0; nt < 4; nt++) {
                    float* c = acc[mt * 4 + nt];
                    asm volatile(
                        "mma.sync.aligned.m16n8k8.row.col.f32.tf32.tf32.f32 "
                        "{%0,%1,%2,%3}, {%4,%5,%6,%7}, {%8,%9}, {%0,%1,%2,%3};"
                        : "+f"(c[0]), "+f"(c[1]), "+f"(c[2]), "+f"(c[3])
                        : "r"(af[mt][0]), "r"(af[mt][1]), "r"(af[mt][2]), "r"(af[mt][3]),
                          "r"(bf[nt][0]), "r"(bf[nt][1]));
                }
        }
        __syncthreads();
    }
    // epilogue: c0/c1 at (row, 2*tig), c2/c3 at (row+8, 2*tig)
#pragma unroll
    for (int mt = 0; mt < 4; mt++) {
        int r = r0 + warp_m * 64 + mt * 16 + gid;
#pragma unroll
        for (int nt = 0; nt < 4; nt++) {
            int c = c0 + warp_n * 32 + nt * 8 + 2 * tig;
            const float* a = acc[mt * 4 + nt];
            float* o0 = g_xl + (size_t)r * EMB + c;
            float* o1 = g_xl + (size_t)(r + 8) * EMB + c;
            o0[0] = a[0]; o0[1] = a[1];
            o1[0] = a[2]; o1[1] = a[3];
        }
    }
}

// as[n] = xl[n].att_src ; ad[n] = xl[n].att_dst   (warp per node)
__global__ void k_asad(const float* __restrict__ att_s, const float* __restrict__ att_d) {
    int gw = (blockIdx.x * blockDim.x + threadIdx.x) >> 5;
    int lane = threadIdx.x & 31;
    if (gw >= NN) return;
    const float4* row = (const float4*)(g_xl + (size_t)gw * EMB);
    const float4* s4 = (const float4*)att_s;
    const float4* d4 = (const float4*)att_d;
    float4 v0 = row[lane], v1 = row[lane + 32];
    float4 s0 = s4[lane], s1 = s4[lane + 32];
    float4 dd0 = d4[lane], dd1 = d4[lane + 32];
    float ss = v0.x * s0.x + v0.y * s0.y + v0.z * s0.z + v0.w * s0.w +
               v1.x * s1.x + v1.y * s1.y + v1.z * s1.z + v1.w * s1.w;
    float dd = v0.x * dd0.x + v0.y * dd0.y + v0.z * dd0.z + v0.w * dd0.w +
               v1.x * dd1.x + v1.y * dd1.y + v1.z * dd1.z + v1.w * dd1.w;
    ss = warp_sum(ss);
    dd = warp_sum(dd);
    if (lane == 0) { g_as[gw] = ss; g_ad[gw] = dd; }
}

// per-node (warp): alpha + leaky + softmax (max/denom), includes self-loop
__global__ void k_alpha() {
    int gw = (blockIdx.x * blockDim.x + threadIdx.x) >> 5;
    int lane = threadIdx.x & 31;
    if (gw >= NN) return;
    int start = g_rowptr[gw], end = g_rowptr[gw + 1];
    float adn = g_ad[gw];
    float mx = -1e30f, esum = 0.f;
    for (int pos = start + lane; pos < end; pos += 32) {
        float ed = g_edot[g_csr_eid[pos]];
        float a = g_as[g_csr_src[pos]] + adn + ed;
        a = (a >= 0.f) ? a : NEG_SLOPE * a;
        g_alpha[pos] = a;
        mx = fmaxf(mx, a);
        esum += ed;
    }
    mx = warp_max(mx);
    esum = warp_sum(esum);
    int deg = end - start;
    float selfa = g_as[gw] + adn + esum / fmaxf((float)deg, 1.0f);
    selfa = (selfa >= 0.f) ? selfa : NEG_SLOPE * selfa;
    float m = fmaxf(mx, selfa);
    float dsum = 0.f;
    for (int pos = start + lane; pos < end; pos += 32) {
        float p = expf(g_alpha[pos] - m);
        g_alpha[pos] = p;
        dsum += p;
    }
    dsum = warp_sum(dsum);
    if (lane == 0) {
        float ws = expf(selfa - m);
        g_wself[gw] = ws;
        g_denom[gw] = dsum + ws;
    }
}

// per-node (warp): out = (sum w*xl[src] + wself*xl[n]) / denom + bias; relu; += h
__global__ void k_aggr(const float* __restrict__ bias, int do_relu) {
    int gw = (blockIdx.x * blockDim.x + threadIdx.x) >> 5;
    int lane = threadIdx.x & 31;
    if (gw >= NN) return;
    int start = g_rowptr[gw], end = g_rowptr[gw + 1];
    float4 acc0 = make_float4(0, 0, 0, 0), acc1 = make_float4(0, 0, 0, 0);
    for (int pos = start; pos < end; pos++) {
        float w = g_alpha[pos];
        int s = g_csr_src[pos];
        const float4* row = (const float4*)(g_xl + (size_t)s * EMB);
        float4 v0 = row[lane], v1 = row[lane + 32];
        acc0.x += w * v0.x; acc0.y += w * v0.y; acc0.z += w * v0.z; acc0.w += w * v0.w;
        acc1.x += w * v1.x; acc1.y += w * v1.y; acc1.z += w * v1.z; acc1.w += w * v1.w;
    }
    {
        float w = g_wself[gw];
        const float4* row = (const float4*)(g_xl + (size_t)gw * EMB);
        float4 v0 = row[lane], v1 = row[lane + 32];
        acc0.x += w * v0.x; acc0.y += w * v0.y; acc0.z += w * v0.z; acc0.w += w * v0.w;
        acc1.x += w * v1.x; acc1.y += w * v1.y; acc1.z += w * v1.z; acc1.w += w * v1.w;
    }
    float inv = 1.0f / g_denom[gw];
    const float4* b4 = (const float4*)bias;
    float4 b0 = b4[lane], b1 = b4[lane + 32];
    float4* hrow = (float4*)(g_h + (size_t)gw * EMB);
    float4 h0 = hrow[lane], h1 = hrow[lane + 32];
    float4 r0, r1;
    r0.x = acc0.x * inv + b0.x; r0.y = acc0.y * inv + b0.y;
    r0.z = acc0.z * inv + b0.z; r0.w = acc0.w * inv + b0.w;
    r1.x = acc1.x * inv + b1.x; r1.y = acc1.y * inv + b1.y;
    r1.z = acc1.z * inv + b1.z; r1.w = acc1.w * inv + b1.w;
    if (do_relu) {
        r0.x = fmaxf(r0.x, 0.f); r0.y = fmaxf(r0.y, 0.f);
        r0.z = fmaxf(r0.z, 0.f); r0.w = fmaxf(r0.w, 0.f);
        r1.x = fmaxf(r1.x, 0.f); r1.y = fmaxf(r1.y, 0.f);
        r1.z = fmaxf(r1.z, 0.f); r1.w = fmaxf(r1.w, 0.f);
    }
    r0.x += h0.x; r0.y += h0.y; r0.z += h0.z; r0.w += h0.w;
    r1.x += h1.x; r1.y += h1.y; r1.z += h1.z; r1.w += h1.w;
    hrow[lane] = r0;
    hrow[lane + 32] = r1;
}

// pooling: s[n] = h[n].wv, atomic into graph buckets
__global__ void k_pool(const int* __restrict__ batch) {
    int gw = (blockIdx.x * blockDim.x + threadIdx.x) >> 5;
    int lane = threadIdx.x & 31;
    if (gw >= NN) return;
    const float4* row = (const float4*)(g_h + (size_t)gw * EMB);
    const float4* w4 = (const float4*)g_wv;
    float4 v0 = row[lane], v1 = row[lane + 32];
    float4 w0 = w4[lane], w1 = w4[lane + 32];
    float s = v0.x * w0.x + v0.y * w0.y + v0.z * w0.z + v0.w * w0.w +
              v1.x * w1.x + v1.y * w1.y + v1.z * w1.z + v1.w * w1.w;
    s = warp_sum(s);
    if (lane == 0) {
        int g = batch[gw];
        atomicAdd(&g_gsum[g], s);
        atomicAdd(&g_gcnt[g], 1.0f);
    }
}

__global__ void k_final(float* __restrict__ out) {
    int g = blockIdx.x * blockDim.x + threadIdx.x;
    if (g < GG) out[g] = g_gsum[g] / fmaxf(g_gcnt[g], 1.0f) + g_bconst;
}

// ---------------- launch -----------------------------------------------------
extern "C" void kernel_launch(void* const* d_in, const int* in_sizes, int n_in,
                              void* d_out, int out_size) {
    const int* x = (const int*)d_in[0];
    const int* edge_index = (const int*)d_in[1];
    const int* edge_attr = (const int*)d_in[2];
    const int* batch = (const int*)d_in[3];
    const float* atom_emb = (const float*)d_in[4];
    const float* bond_emb = (const float*)d_in[5];
    const float* W = (const float*)d_in[6];
    const float* att_src = (const float*)d_in[7];
    const float* att_dst = (const float*)d_in[8];
    const float* We = (const float*)d_in[9];
    const float* att_edge = (const float*)d_in[10];
    const float* bias = (const float*)d_in[11];
    const float* W1 = (const float*)d_in[12];
    const float* b1 = (const float*)d_in[13];
    const float* W2 = (const float*)d_in[14];
    const float* b2 = (const float*)d_in[15];
    float* out = (float*)d_out;

    const int* src = edge_index;
    const int* dst = edge_index + EE;

    const int eblocks = (EE + 255) / 256;
    const int nwarp_blocks = (NN + 7) / 8;  // 8 warps per 256-thread block

    k_init<<<(NPAD * EMB / 256 + 1), 256>>>();
    k_atom<<<NN, 256>>>(x, atom_emb);
    k_hist<<<eblocks, 256>>>(dst);
    k_scan<<<1, 1024>>>();
    k_scatter<<<eblocks, 256>>>(src, dst);
    k_head<<<1, 256>>>(W1, b1, W2, b2);

    for (int l = 0; l < 3; l++) {
        k_lprep<<<1, 96>>>(We, att_edge, bond_emb, l);
        k_edot<<<eblocks, 256>>>(edge_attr);
        k_mma<<<dim3(NPAD / 128, EMB / 128), 256>>>(W + (size_t)l * EMB * EMB);
        k_asad<<<nwarp_blocks, 256>>>(att_src + l * EMB, att_dst + l * EMB);
        k_alpha<<<nwarp_blocks, 256>>>();
        k_aggr<<<nwarp_blocks, 256>>>(bias + l * EMB, (l < 2) ? 1 : 0);
    }

    k_pool<<<nwarp_blocks, 256>>>(batch);
    k_final<<<2, 256>>>(out);
}

// round 3
// speedup vs baseline: 1.6410x; 1.1957x over previous
#include <cuda_runtime.h>
#include <cuda_fp16.h>
#include <math.h>

// Problem constants (fixed shapes for GAT_76184129896720)
#define NN 30000
#define NPAD 30080           // 235 * 128, padded for GEMM
#define EE 480000
#define EMB 256
#define GG 512
#define NEG_SLOPE 0.2f
#define SCB 30               // scan blocks (30*1024 >= NN)

// ---------------- device scratch (static; no allocations allowed) ----------
__device__ float   g_h[NPAD * EMB];    // node features (fp32, residual stream)
__device__ __half2 g_xlh[NPAD * 128];  // h @ W[l] in fp16 (256 halves per row)
__device__ float   g_as[NN];
__device__ float   g_ad[NN];
__device__ int     g_deg[NN];
__device__ int     g_rowptr[NN + 1];
__device__ int     g_cursor[NN];
__device__ int     g_csr_src[EE];
__device__ unsigned g_csr_ea[EE];      // packed bond attrs a0|a1<<8|a2<<16
__device__ int     g_bsum[SCB];
__device__ int     g_boff[SCB];
__device__ float   g_dtable[48];       // 3 x 16 bond scalar LUT (per layer)
__device__ float   g_wv[EMB];          // W1 @ W2
__device__ float   g_bconst;           // b1 @ W2 + b2
__device__ float   g_gsum[GG];
__device__ float   g_gcnt[GG];

// ---------------- helpers ---------------------------------------------------
__device__ __forceinline__ float warp_sum(float v) {
#pragma unroll
    for (int o = 16; o > 0; o >>= 1) v += __shfl_xor_sync(0xffffffffu, v, o);
    return v;
}
__device__ __forceinline__ int warp_sum_i(int v) {
#pragma unroll
    for (int o = 16; o > 0; o >>= 1) v += __shfl_xor_sync(0xffffffffu, v, o);
    return v;
}
__device__ __forceinline__ float warp_max(float v) {
#pragma unroll
    for (int o = 16; o > 0; o >>= 1) v = fmaxf(v, __shfl_xor_sync(0xffffffffu, v, o));
    return v;
}
__device__ __forceinline__ unsigned f2tf(float f) {
    unsigned u;
    asm("cvt.rna.tf32.f32 %0, %1;" : "=r"(u) : "f"(f));
    return u;
}

// ---------------- setup kernels ---------------------------------------------

__global__ void k_init() {
    int i = blockIdx.x * blockDim.x + threadIdx.x;
    if (i < NN) { g_deg[i] = 0; g_cursor[i] = 0; }
    if (i < GG) { g_gsum[i] = 0.f; g_gcnt[i] = 0.f; }
    if (i < (NPAD - NN) * EMB) g_h[NN * EMB + i] = 0.f;
}

// AtomEncoder: h[n][c] = sum_i atom_emb[i][x[n,i]][c]
__global__ void k_atom(const int* __restrict__ x, const float* __restrict__ emb) {
    int n = blockIdx.x;
    int c = threadIdx.x;  // 256
    __shared__ int xi[9];
    if (c < 9) xi[c] = x[n * 9 + c];
    __syncthreads();
    float s = 0.f;
#pragma unroll
    for (int i = 0; i < 9; i++) s += emb[(i * 128 + xi[i]) * EMB + c];
    g_h[n * EMB + c] = s;
}

__global__ void k_hist(const int* __restrict__ dst) {
    int e = blockIdx.x * blockDim.x + threadIdx.x;
    if (e < EE) atomicAdd(&g_deg[dst[e]], 1);
}

// --------- 3-phase multi-block exclusive scan of g_deg -> g_rowptr ----------
__global__ void k_scan_red() {  // grid=SCB, block=1024
    __shared__ int ws[32];
    int t = threadIdx.x, lane = t & 31, wid = t >> 5;
    int idx = blockIdx.x * 1024 + t;
    int v = (idx < NN) ? g_deg[idx] : 0;
    v = warp_sum_i(v);
    if (lane == 0) ws[wid] = v;
    __syncthreads();
    if (wid == 0) {
        int s = ws[lane];
        s = warp_sum_i(s);
        if (lane == 0) g_bsum[blockIdx.x] = s;
    }
}
__global__ void k_scan_top() {  // 1 block, 32 threads
    int lane = threadIdx.x;
    int v = (lane < SCB) ? g_bsum[lane] : 0;
    int x = v;
#pragma unroll
    for (int o = 1; o < 32; o <<= 1) {
        int y = __shfl_up_sync(0xffffffffu, x, o);
        if (lane >= o) x += y;
    }
    if (lane < SCB) g_boff[lane] = x - v;  // exclusive
}
__global__ void k_scan_low() {  // grid=SCB, block=1024
    __shared__ int ws[32];
    int t = threadIdx.x, lane = t & 31, wid = t >> 5;
    int idx = blockIdx.x * 1024 + t;
    int v = (idx < NN) ? g_deg[idx] : 0;
    int x = v;
#pragma unroll
    for (int o = 1; o < 32; o <<= 1) {
        int y = __shfl_up_sync(0xffffffffu, x, o);
        if (lane >= o) x += y;
    }
    if (lane == 31) ws[wid] = x;
    __syncthreads();
    if (wid == 0) {
        int w = ws[lane];
#pragma unroll
        for (int o = 1; o < 32; o <<= 1) {
            int y = __shfl_up_sync(0xffffffffu, w, o);
            if (lane >= o) w += y;
        }
        ws[lane] = w;
    }
    __syncthreads();
    int incl = x + ((wid > 0) ? ws[wid - 1] : 0) + g_boff[blockIdx.x];
    if (idx < NN) g_rowptr[idx + 1] = incl;
    if (idx == 0) g_rowptr[0] = 0;
}

// scatter edges into CSR slots, packing bond attrs
__global__ void k_scatter(const int* __restrict__ src, const int* __restrict__ dst,
                          const int* __restrict__ ea) {
    int e = blockIdx.x * blockDim.x + threadIdx.x;
    if (e >= EE) return;
    int d = dst[e];
    int pos = g_rowptr[d] + atomicAdd(&g_cursor[d], 1);
    g_csr_src[pos] = src[e];
    g_csr_ea[pos] = (unsigned)ea[e * 3 + 0] | ((unsigned)ea[e * 3 + 1] << 8) |
                    ((unsigned)ea[e * 3 + 2] << 16);
}

// head precompute: wv = W1 @ W2, bconst = b1 @ W2 + b2
__global__ void k_head(const float* __restrict__ W1, const float* __restrict__ b1,
                       const float* __restrict__ W2, const float* __restrict__ b2) {
    int c = threadIdx.x;  // 256
    float acc = 0.f;
#pragma unroll 8
    for (int j = 0; j < EMB; j++) acc += W1[c * EMB + j] * W2[j];
    g_wv[c] = acc;
    __shared__ float sh[EMB];
    sh[c] = b1[c] * W2[c];
    __syncthreads();
    for (int s = 128; s > 0; s >>= 1) {
        if (c < s) sh[c] += sh[c + s];
        __syncthreads();
    }
    if (c == 0) g_bconst = sh[0] + b2[0];
}

// per-layer: wa = We[l] @ att_edge[l] (3-vec), then LUT[j][v] = bond_emb[l,j,v,:].wa
__global__ void k_lprep(const float* __restrict__ We, const float* __restrict__ att_edge,
                        const float* __restrict__ bond_emb, int l) {
    __shared__ float wa[3];
    int t = threadIdx.x;  // 96
    int w = t >> 5, lane = t & 31;
    float p = 0.f;
    for (int k = lane; k < EMB; k += 32)
        p += We[(l * 3 + w) * EMB + k] * att_edge[l * EMB + k];
    p = warp_sum(p);
    if (lane == 0) wa[w] = p;
    __syncthreads();
    if (t < 48) {
        int j = t >> 4, v = t & 15;
        const float* be = bond_emb + ((size_t)(l * 3 + j) * 16 + v) * 3;
        g_dtable[t] = be[0] * wa[0] + be[1] * wa[1] + be[2] * wa[2];
    }
}

// ---------------- tf32 tensor-core GEMM: g_xlh = fp16(g_h @ B) ---------------
__global__ __launch_bounds__(256) void k_mma(const float* __restrict__ B) {
    __shared__ unsigned As[32][136];
    __shared__ unsigned Bs[32][136];
    const int tid = threadIdx.x;
    const int lane = tid & 31;
    const int w = tid >> 5;
    const int tig = lane & 3, gid = lane >> 2;
    const int warp_m = w >> 2;   // 0..1
    const int warp_n = w & 3;    // 0..3
    const int r0 = blockIdx.x * 128;
    const int c0 = blockIdx.y * 128;

    const int am = tid & 127;
    const int ak0 = (tid >> 7) * 16;
    const int bn = (tid & 31) * 4;
    const int bk0 = tid >> 5;

    float acc[16][4];
#pragma unroll
    for (int i = 0; i < 16; i++)
#pragma unroll
        for (int j = 0; j < 4; j++) acc[i][j] = 0.f;

    const float* Ag = g_h + (size_t)(r0 + am) * EMB;
    const float* Bg = B + c0 + bn;

    float4 pa[4], pb[4];
#pragma unroll
    for (int i = 0; i < 4; i++) pa[i] = *(const float4*)(Ag + ak0 + 4 * i);
#pragma unroll
    for (int p = 0; p < 4; p++) pb[p] = *(const float4*)(Bg + (size_t)(bk0 + 8 * p) * EMB);

    for (int s = 0; s < 8; s++) {
#pragma unroll
        for (int i = 0; i < 4; i++) {
            int k = ak0 + 4 * i;
            As[k + 0][am] = f2tf(pa[i].x);
            As[k + 1][am] = f2tf(pa[i].y);
            As[k + 2][am] = f2tf(pa[i].z);
            As[k + 3][am] = f2tf(pa[i].w);
        }
#pragma unroll
        for (int p = 0; p < 4; p++) {
            int k = bk0 + 8 * p;
            unsigned b0 = f2tf(pb[p].x), b1 = f2tf(pb[p].y);
            unsigned b2 = f2tf(pb[p].z), b3 = f2tf(pb[p].w);
            *(uint4*)&Bs[k][bn] = make_uint4(b0, b1, b2, b3);
        }
        __syncthreads();
        if (s < 7) {
            int k0 = (s + 1) * 32;
#pragma unroll
            for (int i = 0; i < 4; i++) pa[i] = *(const float4*)(Ag + k0 + ak0 + 4 * i);
#pragma unroll
            for (int p = 0; p < 4; p++)
                pb[p] = *(const float4*)(Bg + (size_t)(k0 + bk0 + 8 * p) * EMB);
        }
#pragma unroll
        for (int kk = 0; kk < 32; kk += 8) {
            unsigned af[4][4], bf[4][2];
#pragma unroll
            for (int mt = 0; mt < 4; mt++) {
                int m = warp_m * 64 + mt * 16 + gid;
                af[mt][0] = As[kk + tig][m];
                af[mt][1] = As[kk + tig][m + 8];
                af[mt][2] = As[kk + tig + 4][m];
                af[mt][3] = As[kk + tig + 4][m + 8];
            }
#pragma unroll
            for (int nt = 0; nt < 4; nt++) {
                int n = warp_n * 32 + nt * 8 + gid;
                bf[nt][0] = Bs[kk + tig][n];
                bf[nt][1] = Bs[kk + tig + 4][n];
            }
#pragma unroll
            for (int mt = 0; mt < 4; mt++)
#pragma unroll
                for (int nt = 0; nt < 4; nt++) {
                    float* c = acc[mt * 4 + nt];
                    asm volatile(
                        "mma.sync.aligned.m16n8k8.row.col.f32.tf32.tf32.f32 "
                        "{%0,%1,%2,%3}, {%4,%5,%6,%7}, {%8,%9}, {%0,%1,%2,%3};"
                        : "+f"(c[0]), "+f"(c[1]), "+f"(c[2]), "+f"(c[3])
                        : "r"(af[mt][0]), "r"(af[mt][1]), "r"(af[mt][2]), "r"(af[mt][3]),
                          "r"(bf[nt][0]), "r"(bf[nt][1]));
                }
        }
        __syncthreads();
    }
    // epilogue: adjacent column pairs -> half2 stores
#pragma unroll
    for (int mt = 0; mt < 4; mt++) {
        int r = r0 + warp_m * 64 + mt * 16 + gid;
#pragma unroll
        for (int nt = 0; nt < 4; nt++) {
            int ch = (c0 + warp_n * 32 + nt * 8 + 2 * tig) >> 1;  // half2 index
            const float* a = acc[mt * 4 + nt];
            g_xlh[(size_t)r * 128 + ch] = __floats2half2_rn(a[0], a[1]);
            g_xlh[(size_t)(r + 8) * 128 + ch] = __floats2half2_rn(a[2], a[3]);
        }
    }
}

// as[n] = xl[n].att_src ; ad[n] = xl[n].att_dst  (warp per node, fp16 xl)
__global__ void k_asad(const float* __restrict__ att_s, const float* __restrict__ att_d) {
    int gw = (blockIdx.x * blockDim.x + threadIdx.x) >> 5;
    int lane = threadIdx.x & 31;
    if (gw >= NN) return;
    uint4 v = *(const uint4*)(g_xlh + (size_t)gw * 128 + lane * 4);  // 8 halves
    const __half2* h2 = (const __half2*)&v;
    float2 f0 = __half22float2(h2[0]), f1 = __half22float2(h2[1]);
    float2 f2 = __half22float2(h2[2]), f3 = __half22float2(h2[3]);
    const float4* s4 = (const float4*)(att_s + lane * 8);
    const float4* d4 = (const float4*)(att_d + lane * 8);
    float4 s0 = s4[0], s1 = s4[1];
    float4 dd0 = d4[0], dd1 = d4[1];
    float ss = f0.x * s0.x + f0.y * s0.y + f1.x * s0.z + f1.y * s0.w +
               f2.x * s1.x + f2.y * s1.y + f3.x * s1.z + f3.y * s1.w;
    float dd = f0.x * dd0.x + f0.y * dd0.y + f1.x * dd0.z + f1.y * dd0.w +
               f2.x * dd1.x + f2.y * dd1.y + f3.x * dd1.z + f3.y * dd1.w;
    ss = warp_sum(ss);
    dd = warp_sum(dd);
    if (lane == 0) { g_as[gw] = ss; g_ad[gw] = dd; }
}

// fused attention: softmax + weighted gather + bias/relu/residual (warp per node)
__global__ void k_att(const float* __restrict__ bias, int do_relu) {
    int gw = (blockIdx.x * blockDim.x + threadIdx.x) >> 5;
    int lane = threadIdx.x & 31;
    if (gw >= NN) return;
    int start = g_rowptr[gw], end = g_rowptr[gw + 1];
    float adn = g_ad[gw];

    // pass A: max + edot sum (for self loop)
    float mx = -1e30f, esum = 0.f;
    for (int pos = start + lane; pos < end; pos += 32) {
        unsigned ea = g_csr_ea[pos];
        float ed = g_dtable[ea & 15] + g_dtable[16 + ((ea >> 8) & 15)] +
                   g_dtable[32 + ((ea >> 16) & 15)];
        float a = g_as[g_csr_src[pos]] + adn + ed;
        a = (a >= 0.f) ? a : NEG_SLOPE * a;
        mx = fmaxf(mx, a);
        esum += ed;
    }
    mx = warp_max(mx);
    esum = warp_sum(esum);
    int deg = end - start;
    float selfa = g_as[gw] + adn + esum / fmaxf((float)deg, 1.0f);
    selfa = (selfa >= 0.f) ? selfa : NEG_SLOPE * selfa;
    float m = fmaxf(mx, selfa);

    // pass B: exp weights + fused weighted row gather (unnormalized)
    float acc[8] = {0, 0, 0, 0, 0, 0, 0, 0};
    float denom = 0.f;
    for (int cb = start; cb < end; cb += 32) {
        int pos = cb + lane;
        float p = 0.f;
        int s = 0;
        if (pos < end) {
            unsigned ea = g_csr_ea[pos];
            float ed = g_dtable[ea & 15] + g_dtable[16 + ((ea >> 8) & 15)] +
                       g_dtable[32 + ((ea >> 16) & 15)];
            s = g_csr_src[pos];
            float a = g_as[s] + adn + ed;
            a = (a >= 0.f) ? a : NEG_SLOPE * a;
            p = __expf(a - m);
        }
        denom += p;
        int cnt = min(32, end - cb);
        for (int i = 0; i < cnt; i++) {
            float w = __shfl_sync(0xffffffffu, p, i);
            int sr = __shfl_sync(0xffffffffu, s, i);
            uint4 v = *(const uint4*)(g_xlh + (size_t)sr * 128 + lane * 4);
            const __half2* h2 = (const __half2*)&v;
            float2 f0 = __half22float2(h2[0]), f1 = __half22float2(h2[1]);
            float2 f2 = __half22float2(h2[2]), f3 = __half22float2(h2[3]);
            acc[0] += w * f0.x; acc[1] += w * f0.y;
            acc[2] += w * f1.x; acc[3] += w * f1.y;
            acc[4] += w * f2.x; acc[5] += w * f2.y;
            acc[6] += w * f3.x; acc[7] += w * f3.y;
        }
    }
    // self loop
    {
        float w = __expf(selfa - m);
        denom = warp_sum(denom) + w;
        uint4 v = *(const uint4*)(g_xlh + (size_t)gw * 128 + lane * 4);
        const __half2* h2 = (const __half2*)&v;
        float2 f0 = __half22float2(h2[0]), f1 = __half22float2(h2[1]);
        float2 f2 = __half22float2(h2[2]), f3 = __half22float2(h2[3]);
        acc[0] += w * f0.x; acc[1] += w * f0.y;
        acc[2] += w * f1.x; acc[3] += w * f1.y;
        acc[4] += w * f2.x; acc[5] += w * f2.y;
        acc[6] += w * f3.x; acc[7] += w * f3.y;
    }
    float inv = 1.0f / denom;
    float* hrow = g_h + (size_t)gw * EMB + lane * 8;
    const float4* b4 = (const float4*)(bias + lane * 8);
    float4 b0 = b4[0], b1 = b4[1];
    float4 h0 = *(float4*)hrow, h1 = *(float4*)(hrow + 4);
    float r[8];
    r[0] = acc[0] * inv + b0.x; r[1] = acc[1] * inv + b0.y;
    r[2] = acc[2] * inv + b0.z; r[3] = acc[3] * inv + b0.w;
    r[4] = acc[4] * inv + b1.x; r[5] = acc[5] * inv + b1.y;
    r[6] = acc[6] * inv + b1.z; r[7] = acc[7] * inv + b1.w;
    if (do_relu) {
#pragma unroll
        for (int j = 0; j < 8; j++) r[j] = fmaxf(r[j], 0.f);
    }
    r[0] += h0.x; r[1] += h0.y; r[2] += h0.z; r[3] += h0.w;
    r[4] += h1.x; r[5] += h1.y; r[6] += h1.z; r[7] += h1.w;
    *(float4*)hrow = make_float4(r[0], r[1], r[2], r[3]);
    *(float4*)(hrow + 4) = make_float4(r[4], r[5], r[6], r[7]);
}

// pooling: s[n] = h[n].wv, atomic into graph buckets
__global__ void k_pool(const int* __restrict__ batch) {
    int gw = (blockIdx.x * blockDim.x + threadIdx.x) >> 5;
    int lane = threadIdx.x & 31;
    if (gw >= NN) return;
    const float4* row = (const float4*)(g_h + (size_t)gw * EMB);
    const float4* w4 = (const float4*)g_wv;
    float4 v0 = row[lane], v1 = row[lane + 32];
    float4 w0 = w4[lane], w1 = w4[lane + 32];
    float s = v0.x * w0.x + v0.y * w0.y + v0.z * w0.z + v0.w * w0.w +
              v1.x * w1.x + v1.y * w1.y + v1.z * w1.z + v1.w * w1.w;
    s = warp_sum(s);
    if (lane == 0) {
        int g = batch[gw];
        atomicAdd(&g_gsum[g], s);
        atomicAdd(&g_gcnt[g], 1.0f);
    }
}

__global__ void k_final(float* __restrict__ out) {
    int g = blockIdx.x * blockDim.x + threadIdx.x;
    if (g < GG) out[g] = g_gsum[g] / fmaxf(g_gcnt[g], 1.0f) + g_bconst;
}

// ---------------- launch -----------------------------------------------------
extern "C" void kernel_launch(void* const* d_in, const int* in_sizes, int n_in,
                              void* d_out, int out_size) {
    const int* x = (const int*)d_in[0];
    const int* edge_index = (const int*)d_in[1];
    const int* edge_attr = (const int*)d_in[2];
    const int* batch = (const int*)d_in[3];
    const float* atom_emb = (const float*)d_in[4];
    const float* bond_emb = (const float*)d_in[5];
    const float* W = (const float*)d_in[6];
    const float* att_src = (const float*)d_in[7];
    const float* att_dst = (const float*)d_in[8];
    const float* We = (const float*)d_in[9];
    const float* att_edge = (const float*)d_in[10];
    const float* bias = (const float*)d_in[11];
    const float* W1 = (const float*)d_in[12];
    const float* b1 = (const float*)d_in[13];
    const float* W2 = (const float*)d_in[14];
    const float* b2 = (const float*)d_in[15];
    float* out = (float*)d_out;

    const int* src = edge_index;
    const int* dst = edge_index + EE;

    const int eblocks = (EE + 255) / 256;
    const int nwarp_blocks = (NN + 7) / 8;  // 8 warps per 256-thread block

    k_init<<<(NPAD * EMB / 256 + 1), 256>>>();
    k_atom<<<NN, 256>>>(x, atom_emb);
    k_hist<<<eblocks, 256>>>(dst);
    k_scan_red<<<SCB, 1024>>>();
    k_scan_top<<<1, 32>>>();
    k_scan_low<<<SCB, 1024>>>();
    k_scatter<<<eblocks, 256>>>(src, dst, edge_attr);
    k_head<<<1, 256>>>(W1, b1, W2, b2);

    for (int l = 0; l < 3; l++) {
        k_lprep<<<1, 96>>>(We, att_edge, bond_emb, l);
        k_mma<<<dim3(NPAD / 128, EMB / 128), 256>>>(W + (size_t)l * EMB * EMB);
        k_asad<<<nwarp_blocks, 256>>>(att_src + l * EMB, att_dst + l * EMB);
        k_att<<<nwarp_blocks, 256>>>(bias + l * EMB, (l < 2) ? 1 : 0);
    }

    k_pool<<<nwarp_blocks, 256>>>(batch);
    k_final<<<2, 256>>>(out);
}

// round 4
// speedup vs baseline: 1.9107x; 1.1643x over previous
#include <cuda_runtime.h>
#include <cuda_fp16.h>
#include <math.h>

// Problem constants (fixed shapes for GAT_76184129896720)
#define NN 30000
#define NPAD 30080           // 235 * 128, padded for GEMM
#define EE 480000
#define EMB 256
#define GG 512
#define NEG_SLOPE 0.2f
#define SCB 30               // scan blocks (30*1024 >= NN)

// ---------------- device scratch (static; no allocations allowed) ----------
__device__ float   g_h[NPAD * EMB];    // node features (fp32, residual stream)
__device__ __half2 g_xlh[NPAD * 128];  // h @ W[l] in fp16 (256 halves per row)
__device__ float   g_as[NN];
__device__ float   g_ad[NN];
__device__ int     g_deg[NN];
__device__ int     g_rowptr[NN + 1];
__device__ int     g_cursor[NN];
__device__ int     g_csr_src[EE];
__device__ unsigned g_csr_ea[EE];      // packed bond attrs a0|a1<<8|a2<<16
__device__ int     g_bsum[SCB];
__device__ int     g_boff[SCB];
__device__ float   g_dtable[48];       // 3 x 16 bond scalar LUT (per layer)
__device__ float   g_wv[EMB];          // W1 @ W2
__device__ float   g_bconst;           // b1 @ W2 + b2
__device__ float   g_gsum[GG];
__device__ float   g_gcnt[GG];

// ---------------- helpers ---------------------------------------------------
__device__ __forceinline__ float warp_sum(float v) {
#pragma unroll
    for (int o = 16; o > 0; o >>= 1) v += __shfl_xor_sync(0xffffffffu, v, o);
    return v;
}
__device__ __forceinline__ int warp_sum_i(int v) {
#pragma unroll
    for (int o = 16; o > 0; o >>= 1) v += __shfl_xor_sync(0xffffffffu, v, o);
    return v;
}
__device__ __forceinline__ float warp_max(float v) {
#pragma unroll
    for (int o = 16; o > 0; o >>= 1) v = fmaxf(v, __shfl_xor_sync(0xffffffffu, v, o));
    return v;
}
__device__ __forceinline__ unsigned packh2(float a, float b) {
    __half2 h = __floats2half2_rn(a, b);
    return *(unsigned*)&h;
}

// ---------------- setup kernels ---------------------------------------------

__global__ void k_init() {
    int i = blockIdx.x * blockDim.x + threadIdx.x;
    if (i < NN) { g_deg[i] = 0; g_cursor[i] = 0; }
    if (i < GG) { g_gsum[i] = 0.f; g_gcnt[i] = 0.f; }
    if (i < (NPAD - NN) * EMB) g_h[NN * EMB + i] = 0.f;
}

// AtomEncoder: h[n][c] = sum_i atom_emb[i][x[n,i]][c]
__global__ void k_atom(const int* __restrict__ x, const float* __restrict__ emb) {
    int n = blockIdx.x;
    int c = threadIdx.x;  // 256
    __shared__ int xi[9];
    if (c < 9) xi[c] = x[n * 9 + c];
    __syncthreads();
    float s = 0.f;
#pragma unroll
    for (int i = 0; i < 9; i++) s += emb[(i * 128 + xi[i]) * EMB + c];
    g_h[n * EMB + c] = s;
}

__global__ void k_hist(const int* __restrict__ dst) {
    int e = blockIdx.x * blockDim.x + threadIdx.x;
    if (e < EE) atomicAdd(&g_deg[dst[e]], 1);
}

// --------- 3-phase multi-block exclusive scan of g_deg -> g_rowptr ----------
__global__ void k_scan_red() {  // grid=SCB, block=1024
    __shared__ int ws[32];
    int t = threadIdx.x, lane = t & 31, wid = t >> 5;
    int idx = blockIdx.x * 1024 + t;
    int v = (idx < NN) ? g_deg[idx] : 0;
    v = warp_sum_i(v);
    if (lane == 0) ws[wid] = v;
    __syncthreads();
    if (wid == 0) {
        int s = ws[lane];
        s = warp_sum_i(s);
        if (lane == 0) g_bsum[blockIdx.x] = s;
    }
}
__global__ void k_scan_top() {  // 1 block, 32 threads
    int lane = threadIdx.x;
    int v = (lane < SCB) ? g_bsum[lane] : 0;
    int x = v;
#pragma unroll
    for (int o = 1; o < 32; o <<= 1) {
        int y = __shfl_up_sync(0xffffffffu, x, o);
        if (lane >= o) x += y;
    }
    if (lane < SCB) g_boff[lane] = x - v;  // exclusive
}
__global__ void k_scan_low() {  // grid=SCB, block=1024
    __shared__ int ws[32];
    int t = threadIdx.x, lane = t & 31, wid = t >> 5;
    int idx = blockIdx.x * 1024 + t;
    int v = (idx < NN) ? g_deg[idx] : 0;
    int x = v;
#pragma unroll
    for (int o = 1; o < 32; o <<= 1) {
        int y = __shfl_up_sync(0xffffffffu, x, o);
        if (lane >= o) x += y;
    }
    if (lane == 31) ws[wid] = x;
    __syncthreads();
    if (wid == 0) {
        int w = ws[lane];
#pragma unroll
        for (int o = 1; o < 32; o <<= 1) {
            int y = __shfl_up_sync(0xffffffffu, w, o);
            if (lane >= o) w += y;
        }
        ws[lane] = w;
    }
    __syncthreads();
    int incl = x + ((wid > 0) ? ws[wid - 1] : 0) + g_boff[blockIdx.x];
    if (idx < NN) g_rowptr[idx + 1] = incl;
    if (idx == 0) g_rowptr[0] = 0;
}

// scatter edges into CSR slots, packing bond attrs
__global__ void k_scatter(const int* __restrict__ src, const int* __restrict__ dst,
                          const int* __restrict__ ea) {
    int e = blockIdx.x * blockDim.x + threadIdx.x;
    if (e >= EE) return;
    int d = dst[e];
    int pos = g_rowptr[d] + atomicAdd(&g_cursor[d], 1);
    g_csr_src[pos] = src[e];
    g_csr_ea[pos] = (unsigned)ea[e * 3 + 0] | ((unsigned)ea[e * 3 + 1] << 8) |
                    ((unsigned)ea[e * 3 + 2] << 16);
}

// head precompute: wv = W1 @ W2, bconst = b1 @ W2 + b2
__global__ void k_head(const float* __restrict__ W1, const float* __restrict__ b1,
                       const float* __restrict__ W2, const float* __restrict__ b2) {
    int c = threadIdx.x;  // 256
    float acc = 0.f;
#pragma unroll 8
    for (int j = 0; j < EMB; j++) acc += W1[c * EMB + j] * W2[j];
    g_wv[c] = acc;
    __shared__ float sh[EMB];
    sh[c] = b1[c] * W2[c];
    __syncthreads();
    for (int s = 128; s > 0; s >>= 1) {
        if (c < s) sh[c] += sh[c + s];
        __syncthreads();
    }
    if (c == 0) g_bconst = sh[0] + b2[0];
}

// per-layer: wa = We[l] @ att_edge[l] (3-vec), then LUT[j][v] = bond_emb[l,j,v,:].wa
__global__ void k_lprep(const float* __restrict__ We, const float* __restrict__ att_edge,
                        const float* __restrict__ bond_emb, int l) {
    __shared__ float wa[3];
    int t = threadIdx.x;  // 96
    int w = t >> 5, lane = t & 31;
    float p = 0.f;
    for (int k = lane; k < EMB; k += 32)
        p += We[(l * 3 + w) * EMB + k] * att_edge[l * EMB + k];
    p = warp_sum(p);
    if (lane == 0) wa[w] = p;
    __syncthreads();
    if (t < 48) {
        int j = t >> 4, v = t & 15;
        const float* be = bond_emb + ((size_t)(l * 3 + j) * 16 + v) * 3;
        g_dtable[t] = be[0] * wa[0] + be[1] * wa[1] + be[2] * wa[2];
    }
}

// ---------------- fp16 tensor-core GEMM: g_xlh = fp16(g_h @ B) ---------------
// Block tile 128x128, K-slab 32, 8 warps (2x4), warp tile 64x32.
// mma.sync.aligned.m16n8k16.row.col.f32.f16.f16.f32
__global__ __launch_bounds__(256) void k_mma(const float* __restrict__ B) {
    __shared__ unsigned As2[16][136];  // [kpair][m], half2 entries (k,k+1)
    __shared__ unsigned Bs2[16][136];  // [kpair][n]
    const int tid = threadIdx.x;
    const int lane = tid & 31;
    const int w = tid >> 5;
    const int tig = lane & 3, gid = lane >> 2;
    const int warp_m = w >> 2;   // 0..1
    const int warp_n = w & 3;    // 0..3
    const int r0 = blockIdx.x * 128;
    const int c0 = blockIdx.y * 128;

    const int am = tid & 127;          // A row within tile
    const int ak0 = (tid >> 7) * 16;   // k base: 0 or 16
    const int bn = (tid & 31) * 4;     // B col group
    const int bk0 = (tid >> 5) * 4;    // k base: 0,4,...,28

    float acc[16][4];
#pragma unroll
    for (int i = 0; i < 16; i++)
#pragma unroll
        for (int j = 0; j < 4; j++) acc[i][j] = 0.f;

    const float* Ag = g_h + (size_t)(r0 + am) * EMB;
    const float* Bg = B + c0 + bn;

    float4 pa[4], pb[4];
#pragma unroll
    for (int i = 0; i < 4; i++) pa[i] = *(const float4*)(Ag + ak0 + 4 * i);
#pragma unroll
    for (int kp = 0; kp < 2; kp++) {
        pb[2 * kp + 0] = *(const float4*)(Bg + (size_t)(bk0 + 2 * kp + 0) * EMB);
        pb[2 * kp + 1] = *(const float4*)(Bg + (size_t)(bk0 + 2 * kp + 1) * EMB);
    }

    for (int s = 0; s < 8; s++) {
        // store prefetched slab to smem as half2
#pragma unroll
        for (int i = 0; i < 4; i++) {
            int kp = (ak0 >> 1) + 2 * i;
            As2[kp + 0][am] = packh2(pa[i].x, pa[i].y);
            As2[kp + 1][am] = packh2(pa[i].z, pa[i].w);
        }
#pragma unroll
        for (int kp = 0; kp < 2; kp++) {
            float4 f0 = pb[2 * kp], f1 = pb[2 * kp + 1];
            uint4 u = make_uint4(packh2(f0.x, f1.x), packh2(f0.y, f1.y),
                                 packh2(f0.z, f1.z), packh2(f0.w, f1.w));
            *(uint4*)&Bs2[(bk0 >> 1) + kp][bn] = u;
        }
        __syncthreads();
        if (s < 7) {
            int k0 = (s + 1) * 32;
#pragma unroll
            for (int i = 0; i < 4; i++) pa[i] = *(const float4*)(Ag + k0 + ak0 + 4 * i);
#pragma unroll
            for (int kp = 0; kp < 2; kp++) {
                pb[2 * kp + 0] = *(const float4*)(Bg + (size_t)(k0 + bk0 + 2 * kp + 0) * EMB);
                pb[2 * kp + 1] = *(const float4*)(Bg + (size_t)(k0 + bk0 + 2 * kp + 1) * EMB);
            }
        }
#pragma unroll
        for (int kk2 = 0; kk2 < 16; kk2 += 8) {  // two k16 steps per slab
            unsigned af[4][4], bf[4][2];
#pragma unroll
            for (int mt = 0; mt < 4; mt++) {
                int m = warp_m * 64 + mt * 16 + gid;
                af[mt][0] = As2[kk2 + tig][m];
                af[mt][1] = As2[kk2 + tig][m + 8];
                af[mt][2] = As2[kk2 + tig + 4][m];
                af[mt][3] = As2[kk2 + tig + 4][m + 8];
            }
#pragma unroll
            for (int nt = 0; nt < 4; nt++) {
                int n = warp_n * 32 + nt * 8 + gid;
                bf[nt][0] = Bs2[kk2 + tig][n];
                bf[nt][1] = Bs2[kk2 + tig + 4][n];
            }
#pragma unroll
            for (int mt = 0; mt < 4; mt++)
#pragma unroll
                for (int nt = 0; nt < 4; nt++) {
                    float* c = acc[mt * 4 + nt];
                    asm volatile(
                        "mma.sync.aligned.m16n8k16.row.col.f32.f16.f16.f32 "
                        "{%0,%1,%2,%3}, {%4,%5,%6,%7}, {%8,%9}, {%0,%1,%2,%3};"
                        : "+f"(c[0]), "+f"(c[1]), "+f"(c[2]), "+f"(c[3])
                        : "r"(af[mt][0]), "r"(af[mt][1]), "r"(af[mt][2]), "r"(af[mt][3]),
                          "r"(bf[nt][0]), "r"(bf[nt][1]));
                }
        }
        __syncthreads();
    }
    // epilogue: adjacent column pairs -> half2 stores
#pragma unroll
    for (int mt = 0; mt < 4; mt++) {
        int r = r0 + warp_m * 64 + mt * 16 + gid;
#pragma unroll
        for (int nt = 0; nt < 4; nt++) {
            int ch = (c0 + warp_n * 32 + nt * 8 + 2 * tig) >> 1;  // half2 index
            const float* a = acc[mt * 4 + nt];
            g_xlh[(size_t)r * 128 + ch] = __floats2half2_rn(a[0], a[1]);
            g_xlh[(size_t)(r + 8) * 128 + ch] = __floats2half2_rn(a[2], a[3]);
        }
    }
}

// as[n] = xl[n].att_src ; ad[n] = xl[n].att_dst  (warp per node, fp16 xl)
__global__ void k_asad(const float* __restrict__ att_s, const float* __restrict__ att_d) {
    int gw = (blockIdx.x * blockDim.x + threadIdx.x) >> 5;
    int lane = threadIdx.x & 31;
    if (gw >= NN) return;
    uint4 v = *(const uint4*)(g_xlh + (size_t)gw * 128 + lane * 4);  // 8 halves
    const __half2* h2 = (const __half2*)&v;
    float2 f0 = __half22float2(h2[0]), f1 = __half22float2(h2[1]);
    float2 f2 = __half22float2(h2[2]), f3 = __half22float2(h2[3]);
    const float4* s4 = (const float4*)(att_s + lane * 8);
    const float4* d4 = (const float4*)(att_d + lane * 8);
    float4 s0 = s4[0], s1 = s4[1];
    float4 dd0 = d4[0], dd1 = d4[1];
    float ss = f0.x * s0.x + f0.y * s0.y + f1.x * s0.z + f1.y * s0.w +
               f2.x * s1.x + f2.y * s1.y + f3.x * s1.z + f3.y * s1.w;
    float dd = f0.x * dd0.x + f0.y * dd0.y + f1.x * dd0.z + f1.y * dd0.w +
               f2.x * dd1.x + f2.y * dd1.y + f3.x * dd1.z + f3.y * dd1.w;
    ss = warp_sum(ss);
    dd = warp_sum(dd);
    if (lane == 0) { g_as[gw] = ss; g_ad[gw] = dd; }
}

// fused attention: softmax + weighted gather + bias/relu/residual (warp per node)
__global__ void k_att(const float* __restrict__ bias, int do_relu) {
    int gw = (blockIdx.x * blockDim.x + threadIdx.x) >> 5;
    int lane = threadIdx.x & 31;
    if (gw >= NN) return;
    int start = g_rowptr[gw], end = g_rowptr[gw + 1];
    float adn = g_ad[gw];

    // pass A: max + edot sum (for self loop)
    float mx = -1e30f, esum = 0.f;
    for (int pos = start + lane; pos < end; pos += 32) {
        unsigned ea = g_csr_ea[pos];
        float ed = g_dtable[ea & 15] + g_dtable[16 + ((ea >> 8) & 15)] +
                   g_dtable[32 + ((ea >> 16) & 15)];
        float a = g_as[g_csr_src[pos]] + adn + ed;
        a = (a >= 0.f) ? a : NEG_SLOPE * a;
        mx = fmaxf(mx, a);
        esum += ed;
    }
    mx = warp_max(mx);
    esum = warp_sum(esum);
    int deg = end - start;
    float selfa = g_as[gw] + adn + esum / fmaxf((float)deg, 1.0f);
    selfa = (selfa >= 0.f) ? selfa : NEG_SLOPE * selfa;
    float m = fmaxf(mx, selfa);

    // pass B: exp weights + weighted row gather with 1-deep row prefetch
    float acc[8] = {0, 0, 0, 0, 0, 0, 0, 0};
    float denom = 0.f;
    for (int cb = start; cb < end; cb += 32) {
        int pos = cb + lane;
        float p = 0.f;
        int s = 0;
        if (pos < end) {
            unsigned ea = g_csr_ea[pos];
            float ed = g_dtable[ea & 15] + g_dtable[16 + ((ea >> 8) & 15)] +
                       g_dtable[32 + ((ea >> 16) & 15)];
            s = g_csr_src[pos];
            float a = g_as[s] + adn + ed;
            a = (a >= 0.f) ? a : NEG_SLOPE * a;
            p = __expf(a - m);
        }
        denom += p;
        int cnt = min(32, end - cb);
        float w = __shfl_sync(0xffffffffu, p, 0);
        int sr = __shfl_sync(0xffffffffu, s, 0);
        uint4 v = *(const uint4*)(g_xlh + (size_t)sr * 128 + lane * 4);
        for (int i = 0; i < cnt; i++) {
            uint4 vn = make_uint4(0, 0, 0, 0);
            float wn = 0.f;
            if (i + 1 < cnt) {
                wn = __shfl_sync(0xffffffffu, p, i + 1);
                int srn = __shfl_sync(0xffffffffu, s, i + 1);
                vn = *(const uint4*)(g_xlh + (size_t)srn * 128 + lane * 4);
            }
            const __half2* h2 = (const __half2*)&v;
            float2 f0 = __half22float2(h2[0]), f1 = __half22float2(h2[1]);
            float2 f2 = __half22float2(h2[2]), f3 = __half22float2(h2[3]);
            acc[0] += w * f0.x; acc[1] += w * f0.y;
            acc[2] += w * f1.x; acc[3] += w * f1.y;
            acc[4] += w * f2.x; acc[5] += w * f2.y;
            acc[6] += w * f3.x; acc[7] += w * f3.y;
            v = vn;
            w = wn;
        }
    }
    // self loop
    {
        float w = __expf(selfa - m);
        denom = warp_sum(denom) + w;
        uint4 v = *(const uint4*)(g_xlh + (size_t)gw * 128 + lane * 4);
        const __half2* h2 = (const __half2*)&v;
        float2 f0 = __half22float2(h2[0]), f1 = __half22float2(h2[1]);
        float2 f2 = __half22float2(h2[2]), f3 = __half22float2(h2[3]);
        acc[0] += w * f0.x; acc[1] += w * f0.y;
        acc[2] += w * f1.x; acc[3] += w * f1.y;
        acc[4] += w * f2.x; acc[5] += w * f2.y;
        acc[6] += w * f3.x; acc[7] += w * f3.y;
    }
    float inv = 1.0f / denom;
    float* hrow = g_h + (size_t)gw * EMB + lane * 8;
    const float4* b4 = (const float4*)(bias + lane * 8);
    float4 b0 = b4[0], b1 = b4[1];
    float4 h0 = *(float4*)hrow, h1 = *(float4*)(hrow + 4);
    float r[8];
    r[0] = acc[0] * inv + b0.x; r[1] = acc[1] * inv + b0.y;
    r[2] = acc[2] * inv + b0.z; r[3] = acc[3] * inv + b0.w;
    r[4] = acc[4] * inv + b1.x; r[5] = acc[5] * inv + b1.y;
    r[6] = acc[6] * inv + b1.z; r[7] = acc[7] * inv + b1.w;
    if (do_relu) {
#pragma unroll
        for (int j = 0; j < 8; j++) r[j] = fmaxf(r[j], 0.f);
    }
    r[0] += h0.x; r[1] += h0.y; r[2] += h0.z; r[3] += h0.w;
    r[4] += h1.x; r[5] += h1.y; r[6] += h1.z; r[7] += h1.w;
    *(float4*)hrow = make_float4(r[0], r[1], r[2], r[3]);
    *(float4*)(hrow + 4) = make_float4(r[4], r[5], r[6], r[7]);
}

// pooling: s[n] = h[n].wv, atomic into graph buckets
__global__ void k_pool(const int* __restrict__ batch) {
    int gw = (blockIdx.x * blockDim.x + threadIdx.x) >> 5;
    int lane = threadIdx.x & 31;
    if (gw >= NN) return;
    const float4* row = (const float4*)(g_h + (size_t)gw * EMB);
    const float4* w4 = (const float4*)g_wv;
    float4 v0 = row[lane], v1 = row[lane + 32];
    float4 w0 = w4[lane], w1 = w4[lane + 32];
    float s = v0.x * w0.x + v0.y * w0.y + v0.z * w0.z + v0.w * w0.w +
              v1.x * w1.x + v1.y * w1.y + v1.z * w1.z + v1.w * w1.w;
    s = warp_sum(s);
    if (lane == 0) {
        int g = batch[gw];
        atomicAdd(&g_gsum[g], s);
        atomicAdd(&g_gcnt[g], 1.0f);
    }
}

__global__ void k_final(float* __restrict__ out) {
    int g = blockIdx.x * blockDim.x + threadIdx.x;
    if (g < GG) out[g] = g_gsum[g] / fmaxf(g_gcnt[g], 1.0f) + g_bconst;
}

// ---------------- launch -----------------------------------------------------
extern "C" void kernel_launch(void* const* d_in, const int* in_sizes, int n_in,
                              void* d_out, int out_size) {
    const int* x = (const int*)d_in[0];
    const int* edge_index = (const int*)d_in[1];
    const int* edge_attr = (const int*)d_in[2];
    const int* batch = (const int*)d_in[3];
    const float* atom_emb = (const float*)d_in[4];
    const float* bond_emb = (const float*)d_in[5];
    const float* W = (const float*)d_in[6];
    const float* att_src = (const float*)d_in[7];
    const float* att_dst = (const float*)d_in[8];
    const float* We = (const float*)d_in[9];
    const float* att_edge = (const float*)d_in[10];
    const float* bias = (const float*)d_in[11];
    const float* W1 = (const float*)d_in[12];
    const float* b1 = (const float*)d_in[13];
    const float* W2 = (const float*)d_in[14];
    const float* b2 = (const float*)d_in[15];
    float* out = (float*)d_out;

    const int* src = edge_index;
    const int* dst = edge_index + EE;

    const int eblocks = (EE + 255) / 256;
    const int nwarp_blocks = (NN + 7) / 8;  // 8 warps per 256-thread block

    k_init<<<(NN + 255) / 256, 256>>>();
    k_atom<<<NN, 256>>>(x, atom_emb);
    k_hist<<<eblocks, 256>>>(dst);
    // layer-0 GEMM placed 4th so the ncu capture (4th launch) profiles it
    k_mma<<<dim3(NPAD / 128, EMB / 128), 256>>>(W);
    k_scan_red<<<SCB, 1024>>>();
    k_scan_top<<<1, 32>>>();
    k_scan_low<<<SCB, 1024>>>();
    k_scatter<<<eblocks, 256>>>(src, dst, edge_attr);
    k_head<<<1, 256>>>(W1, b1, W2, b2);

    for (int l = 0; l < 3; l++) {
        k_lprep<<<1, 96>>>(We, att_edge, bond_emb, l);
        if (l > 0) k_mma<<<dim3(NPAD / 128, EMB / 128), 256>>>(W + (size_t)l * EMB * EMB);
        k_asad<<<nwarp_blocks, 256>>>(att_src + l * EMB, att_dst + l * EMB);
        k_att<<<nwarp_blocks, 256>>>(bias + l * EMB, (l < 2) ? 1 : 0);
    }

    k_pool<<<nwarp_blocks, 256>>>(batch);
    k_final<<<2, 256>>>(out);
}

// round 5
// speedup vs baseline: 1.9118x; 1.0006x over previous
#include <cuda_runtime.h>
#include <cuda_fp16.h>
#include <math.h>

// Problem constants (fixed shapes for GAT_76184129896720)
#define NN 30000
#define NPAD 30080           // 235 * 128, padded for GEMM
#define EE 480000
#define EMB 256
#define GG 512
#define NEG_SLOPE 0.2f
#define SCB 30               // scan blocks (30*1024 >= NN)

// ---------------- device scratch (static; no allocations allowed) ----------
__device__ float   g_h[NPAD * EMB];    // node features (fp32, residual stream)
__device__ __half  g_h16[NPAD * EMB];  // fp16 shadow of h (GEMM A input)
__device__ __half  g_w16[3 * EMB * EMB]; // per-layer W, fp16, transposed [n][k]
__device__ __half2 g_xlh[NPAD * 128];  // h @ W[l] in fp16 (256 halves per row)
__device__ float   g_as[NN];
__device__ float   g_ad[NN];
__device__ int     g_deg[NN];
__device__ int     g_rowptr[NN + 1];
__device__ int     g_cursor[NN];
__device__ int     g_csr_src[EE];
__device__ unsigned g_csr_ea[EE];      // packed bond attrs a0|a1<<8|a2<<16
__device__ int     g_bsum[SCB];
__device__ int     g_boff[SCB];
__device__ float   g_dtable[48];       // 3 x 16 bond scalar LUT (per layer)
__device__ float   g_wv[EMB];          // W1 @ W2
__device__ float   g_bconst;           // b1 @ W2 + b2
__device__ float   g_gsum[GG];
__device__ float   g_gcnt[GG];

// ---------------- helpers ---------------------------------------------------
__device__ __forceinline__ float warp_sum(float v) {
#pragma unroll
    for (int o = 16; o > 0; o >>= 1) v += __shfl_xor_sync(0xffffffffu, v, o);
    return v;
}
__device__ __forceinline__ int warp_sum_i(int v) {
#pragma unroll
    for (int o = 16; o > 0; o >>= 1) v += __shfl_xor_sync(0xffffffffu, v, o);
    return v;
}
__device__ __forceinline__ float warp_max(float v) {
#pragma unroll
    for (int o = 16; o > 0; o >>= 1) v = fmaxf(v, __shfl_xor_sync(0xffffffffu, v, o));
    return v;
}
__device__ __forceinline__ void cp16(unsigned dst, const void* src) {
    asm volatile("cp.async.cg.shared.global [%0], [%1], 16;" :: "r"(dst), "l"(src));
}
__device__ __forceinline__ void ldsm4(unsigned addr, unsigned& r0, unsigned& r1,
                                      unsigned& r2, unsigned& r3) {
    asm volatile("ldmatrix.sync.aligned.m8n8.x4.shared.b16 {%0,%1,%2,%3}, [%4];"
                 : "=r"(r0), "=r"(r1), "=r"(r2), "=r"(r3) : "r"(addr));
}
// smem tile layout: 2 logical rows per 128B physical row, XOR swizzle.
// m: logical row 0..127, kc: 16B chunk within 32-half slab (0..3)
__device__ __forceinline__ int swoff(int m, int kc) {
    int p = m >> 1;
    int c = ((m & 1) << 2) | (kc ^ (p & 3));
    return p * 128 + c * 16;
}

// ---------------- setup kernels ---------------------------------------------

__global__ void k_init() {
    int i = blockIdx.x * blockDim.x + threadIdx.x;
    if (i < NN) { g_deg[i] = 0; g_cursor[i] = 0; }
    if (i < GG) { g_gsum[i] = 0.f; g_gcnt[i] = 0.f; }
    if (i < (NPAD - NN) * EMB) {
        g_h[NN * EMB + i] = 0.f;
        g_h16[NN * EMB + i] = __float2half(0.f);
    }
}

// AtomEncoder: h[n][c] = sum_i atom_emb[i][x[n,i]][c]  (+ fp16 shadow)
__global__ void k_atom(const int* __restrict__ x, const float* __restrict__ emb) {
    int n = blockIdx.x;
    int c = threadIdx.x;  // 256
    __shared__ int xi[9];
    if (c < 9) xi[c] = x[n * 9 + c];
    __syncthreads();
    float s = 0.f;
#pragma unroll
    for (int i = 0; i < 9; i++) s += emb[(i * 128 + xi[i]) * EMB + c];
    g_h[n * EMB + c] = s;
    g_h16[n * EMB + c] = __float2half(s);
}

// convert + transpose weights: g_w16[l][n][k] = fp16(W[l][k][n])
__global__ void k_wconv(const float* __restrict__ W) {
    __shared__ float tile[32][33];
    int l = blockIdx.z;
    int kb = blockIdx.x * 32, nb = blockIdx.y * 32;
    for (int i = threadIdx.y; i < 32; i += 8)
        tile[i][threadIdx.x] = W[(size_t)l * EMB * EMB + (kb + i) * EMB + nb + threadIdx.x];
    __syncthreads();
    for (int i = threadIdx.y; i < 32; i += 8)
        g_w16[(size_t)l * EMB * EMB + (nb + i) * EMB + kb + threadIdx.x] =
            __float2half(tile[threadIdx.x][i]);
}

__global__ void k_hist(const int* __restrict__ dst) {
    int e = blockIdx.x * blockDim.x + threadIdx.x;
    if (e < EE) atomicAdd(&g_deg[dst[e]], 1);
}

// --------- 3-phase multi-block exclusive scan of g_deg -> g_rowptr ----------
__global__ void k_scan_red() {
    __shared__ int ws[32];
    int t = threadIdx.x, lane = t & 31, wid = t >> 5;
    int idx = blockIdx.x * 1024 + t;
    int v = (idx < NN) ? g_deg[idx] : 0;
    v = warp_sum_i(v);
    if (lane == 0) ws[wid] = v;
    __syncthreads();
    if (wid == 0) {
        int s = ws[lane];
        s = warp_sum_i(s);
        if (lane == 0) g_bsum[blockIdx.x] = s;
    }
}
__global__ void k_scan_top() {
    int lane = threadIdx.x;
    int v = (lane < SCB) ? g_bsum[lane] : 0;
    int x = v;
#pragma unroll
    for (int o = 1; o < 32; o <<= 1) {
        int y = __shfl_up_sync(0xffffffffu, x, o);
        if (lane >= o) x += y;
    }
    if (lane < SCB) g_boff[lane] = x - v;
}
__global__ void k_scan_low() {
    __shared__ int ws[32];
    int t = threadIdx.x, lane = t & 31, wid = t >> 5;
    int idx = blockIdx.x * 1024 + t;
    int v = (idx < NN) ? g_deg[idx] : 0;
    int x = v;
#pragma unroll
    for (int o = 1; o < 32; o <<= 1) {
        int y = __shfl_up_sync(0xffffffffu, x, o);
        if (lane >= o) x += y;
    }
    if (lane == 31) ws[wid] = x;
    __syncthreads();
    if (wid == 0) {
        int w = ws[lane];
#pragma unroll
        for (int o = 1; o < 32; o <<= 1) {
            int y = __shfl_up_sync(0xffffffffu, w, o);
            if (lane >= o) w += y;
        }
        ws[lane] = w;
    }
    __syncthreads();
    int incl = x + ((wid > 0) ? ws[wid - 1] : 0) + g_boff[blockIdx.x];
    if (idx < NN) g_rowptr[idx + 1] = incl;
    if (idx == 0) g_rowptr[0] = 0;
}

__global__ void k_scatter(const int* __restrict__ src, const int* __restrict__ dst,
                          const int* __restrict__ ea) {
    int e = blockIdx.x * blockDim.x + threadIdx.x;
    if (e >= EE) return;
    int d = dst[e];
    int pos = g_rowptr[d] + atomicAdd(&g_cursor[d], 1);
    g_csr_src[pos] = src[e];
    g_csr_ea[pos] = (unsigned)ea[e * 3 + 0] | ((unsigned)ea[e * 3 + 1] << 8) |
                    ((unsigned)ea[e * 3 + 2] << 16);
}

__global__ void k_head(const float* __restrict__ W1, const float* __restrict__ b1,
                       const float* __restrict__ W2, const float* __restrict__ b2) {
    int c = threadIdx.x;
    float acc = 0.f;
#pragma unroll 8
    for (int j = 0; j < EMB; j++) acc += W1[c * EMB + j] * W2[j];
    g_wv[c] = acc;
    __shared__ float sh[EMB];
    sh[c] = b1[c] * W2[c];
    __syncthreads();
    for (int s = 128; s > 0; s >>= 1) {
        if (c < s) sh[c] += sh[c + s];
        __syncthreads();
    }
    if (c == 0) g_bconst = sh[0] + b2[0];
}

__global__ void k_lprep(const float* __restrict__ We, const float* __restrict__ att_edge,
                        const float* __restrict__ bond_emb, int l) {
    __shared__ float wa[3];
    int t = threadIdx.x;  // 96
    int w = t >> 5, lane = t & 31;
    float p = 0.f;
    for (int k = lane; k < EMB; k += 32)
        p += We[(l * 3 + w) * EMB + k] * att_edge[l * EMB + k];
    p = warp_sum(p);
    if (lane == 0) wa[w] = p;
    __syncthreads();
    if (t < 48) {
        int j = t >> 4, v = t & 15;
        const float* be = bond_emb + ((size_t)(l * 3 + j) * 16 + v) * 3;
        g_dtable[t] = be[0] * wa[0] + be[1] * wa[1] + be[2] * wa[2];
    }
}

// ------- fp16 GEMM: g_xlh = fp16(g_h16 @ g_w16[l]^T-layout), cp.async+ldmatrix
// Block 128x128, K slab 32, 3-stage pipeline, 8 warps (2x4), warp tile 64x32.
__global__ __launch_bounds__(256) void k_mma(int l) {
    __shared__ __align__(16) char sm[49152];  // 3 stages x (A 8KB + B 8KB)
    const unsigned smb = (unsigned)__cvta_generic_to_shared(sm);
    const int tid = threadIdx.x;
    const int lane = tid & 31;
    const int w = tid >> 5;
    const int tig = lane & 3, gid = lane >> 2;
    const int warp_m = w >> 2, warp_n = w & 3;
    const int r0 = blockIdx.x * 128, c0 = blockIdx.y * 128;

    const int lm = tid & 127;
    const int lkc = (tid >> 7) * 2;  // chunk base 0 or 2
    const __half* Ag = g_h16 + (size_t)(r0 + lm) * EMB + lkc * 8;
    const __half* Bg = g_w16 + (size_t)l * EMB * EMB + (size_t)(c0 + lm) * EMB + lkc * 8;
    const int sA0 = swoff(lm, lkc), sA1 = swoff(lm, lkc + 1);

    float acc[16][4];
#pragma unroll
    for (int i = 0; i < 16; i++)
#pragma unroll
        for (int j = 0; j < 4; j++) acc[i][j] = 0.f;

#define ISSUE(s)                                                          \
    {                                                                     \
        unsigned st = smb + ((s) % 3) * 16384;                            \
        cp16(st + sA0, Ag + (s) * 32);                                    \
        cp16(st + sA1, Ag + (s) * 32 + 8);                                \
        cp16(st + 8192 + sA0, Bg + (s) * 32);                             \
        cp16(st + 8192 + sA1, Bg + (s) * 32 + 8);                         \
        asm volatile("cp.async.commit_group;");                           \
    }

    ISSUE(0);
    ISSUE(1);

#pragma unroll
    for (int s = 0; s < 8; s++) {
        if (s < 7) asm volatile("cp.async.wait_group 1;");
        else       asm volatile("cp.async.wait_group 0;");
        __syncthreads();
        if (s + 2 < 8) ISSUE(s + 2);
        unsigned Ab = smb + (s % 3) * 16384;
        unsigned Bb = Ab + 8192;
#pragma unroll
        for (int kk = 0; kk < 32; kk += 16) {
            unsigned af[4][4], bf[4][2];
#pragma unroll
            for (int mt = 0; mt < 4; mt++) {
                int r = warp_m * 64 + mt * 16 + (lane & 15);
                int kc = (kk >> 3) + (lane >> 4);
                ldsm4(Ab + swoff(r, kc), af[mt][0], af[mt][1], af[mt][2], af[mt][3]);
            }
#pragma unroll
            for (int pr = 0; pr < 2; pr++) {
                int n = warp_n * 32 + pr * 16 + ((lane >> 4) & 1) * 8 + (lane & 7);
                int kc = (kk >> 3) + ((lane >> 3) & 1);
                ldsm4(Bb + swoff(n, kc), bf[2 * pr][0], bf[2 * pr][1],
                      bf[2 * pr + 1][0], bf[2 * pr + 1][1]);
            }
#pragma unroll
            for (int mt = 0; mt < 4; mt++)
#pragma unroll
                for (int nt = 0; nt < 4; nt++) {
                    float* c = acc[mt * 4 + nt];
                    asm volatile(
                        "mma.sync.aligned.m16n8k16.row.col.f32.f16.f16.f32 "
                        "{%0,%1,%2,%3}, {%4,%5,%6,%7}, {%8,%9}, {%0,%1,%2,%3};"
                        : "+f"(c[0]), "+f"(c[1]), "+f"(c[2]), "+f"(c[3])
                        : "r"(af[mt][0]), "r"(af[mt][1]), "r"(af[mt][2]), "r"(af[mt][3]),
                          "r"(bf[nt][0]), "r"(bf[nt][1]));
                }
        }
    }
#undef ISSUE
    // epilogue: c0/c1 at (row, 2tig), c2/c3 at (row+8, 2tig)
#pragma unroll
    for (int mt = 0; mt < 4; mt++) {
        int r = r0 + warp_m * 64 + mt * 16 + gid;
#pragma unroll
        for (int nt = 0; nt < 4; nt++) {
            int ch = (c0 + warp_n * 32 + nt * 8 + 2 * tig) >> 1;
            const float* a = acc[mt * 4 + nt];
            g_xlh[(size_t)r * 128 + ch] = __floats2half2_rn(a[0], a[1]);
            g_xlh[(size_t)(r + 8) * 128 + ch] = __floats2half2_rn(a[2], a[3]);
        }
    }
}

// as[n] = xl[n].att_src ; ad[n] = xl[n].att_dst  (warp per node, fp16 xl)
__global__ void k_asad(const float* __restrict__ att_s, const float* __restrict__ att_d) {
    int gw = (blockIdx.x * blockDim.x + threadIdx.x) >> 5;
    int lane = threadIdx.x & 31;
    if (gw >= NN) return;
    uint4 v = *(const uint4*)(g_xlh + (size_t)gw * 128 + lane * 4);
    const __half2* h2 = (const __half2*)&v;
    float2 f0 = __half22float2(h2[0]), f1 = __half22float2(h2[1]);
    float2 f2 = __half22float2(h2[2]), f3 = __half22float2(h2[3]);
    const float4* s4 = (const float4*)(att_s + lane * 8);
    const float4* d4 = (const float4*)(att_d + lane * 8);
    float4 s0 = s4[0], s1 = s4[1];
    float4 dd0 = d4[0], dd1 = d4[1];
    float ss = f0.x * s0.x + f0.y * s0.y + f1.x * s0.z + f1.y * s0.w +
               f2.x * s1.x + f2.y * s1.y + f3.x * s1.z + f3.y * s1.w;
    float dd = f0.x * dd0.x + f0.y * dd0.y + f1.x * dd0.z + f1.y * dd0.w +
               f2.x * dd1.x + f2.y * dd1.y + f3.x * dd1.z + f3.y * dd1.w;
    ss = warp_sum(ss);
    dd = warp_sum(dd);
    if (lane == 0) { g_as[gw] = ss; g_ad[gw] = dd; }
}

// fused attention: softmax + weighted gather + bias/relu/residual (warp per node)
__global__ void k_att(const float* __restrict__ bias, int do_relu) {
    int gw = (blockIdx.x * blockDim.x + threadIdx.x) >> 5;
    int lane = threadIdx.x & 31;
    if (gw >= NN) return;
    int start = g_rowptr[gw], end = g_rowptr[gw + 1];
    float adn = g_ad[gw];

    // pass A: max + edot sum (for self loop)
    float mx = -1e30f, esum = 0.f;
    for (int pos = start + lane; pos < end; pos += 32) {
        unsigned ea = g_csr_ea[pos];
        float ed = g_dtable[ea & 15] + g_dtable[16 + ((ea >> 8) & 15)] +
                   g_dtable[32 + ((ea >> 16) & 15)];
        float a = g_as[g_csr_src[pos]] + adn + ed;
        a = (a >= 0.f) ? a : NEG_SLOPE * a;
        mx = fmaxf(mx, a);
        esum += ed;
    }
    mx = warp_max(mx);
    esum = warp_sum(esum);
    int deg = end - start;
    float selfa = g_as[gw] + adn + esum / fmaxf((float)deg, 1.0f);
    selfa = (selfa >= 0.f) ? selfa : NEG_SLOPE * selfa;
    float m = fmaxf(mx, selfa);

    // pass B: exp weights + weighted row gather, depth-2 pipelined
    float acc[8] = {0, 0, 0, 0, 0, 0, 0, 0};
    float denom = 0.f;
    for (int cb = start; cb < end; cb += 32) {
        int pos = cb + lane;
        float p = 0.f;
        int s = 0;
        if (pos < end) {
            unsigned ea = g_csr_ea[pos];
            float ed = g_dtable[ea & 15] + g_dtable[16 + ((ea >> 8) & 15)] +
                       g_dtable[32 + ((ea >> 16) & 15)];
            s = g_csr_src[pos];
            float a = g_as[s] + adn + ed;
            a = (a >= 0.f) ? a : NEG_SLOPE * a;
            p = __expf(a - m);
        }
        denom += p;
        int cnt = min(32, end - cb);
        uint4 va = make_uint4(0, 0, 0, 0), vb = make_uint4(0, 0, 0, 0);
        float wa = 0.f, wb = 0.f;
        if (cnt > 0) {
            wa = __shfl_sync(0xffffffffu, p, 0);
            int s0 = __shfl_sync(0xffffffffu, s, 0);
            va = *(const uint4*)(g_xlh + (size_t)s0 * 128 + lane * 4);
        }
        if (cnt > 1) {
            wb = __shfl_sync(0xffffffffu, p, 1);
            int s1 = __shfl_sync(0xffffffffu, s, 1);
            vb = *(const uint4*)(g_xlh + (size_t)s1 * 128 + lane * 4);
        }
        for (int i = 0; i < cnt; i += 2) {
            uint4 v = va;
            float wv = wa;
            if (i + 2 < cnt) {
                wa = __shfl_sync(0xffffffffu, p, i + 2);
                int sn = __shfl_sync(0xffffffffu, s, i + 2);
                va = *(const uint4*)(g_xlh + (size_t)sn * 128 + lane * 4);
            }
            {
                const __half2* h2 = (const __half2*)&v;
                float2 f0 = __half22float2(h2[0]), f1 = __half22float2(h2[1]);
                float2 f2 = __half22float2(h2[2]), f3 = __half22float2(h2[3]);
                acc[0] += wv * f0.x; acc[1] += wv * f0.y;
                acc[2] += wv * f1.x; acc[3] += wv * f1.y;
                acc[4] += wv * f2.x; acc[5] += wv * f2.y;
                acc[6] += wv * f3.x; acc[7] += wv * f3.y;
            }
            if (i + 1 < cnt) {
                uint4 v2 = vb;
                float w2 = wb;
                if (i + 3 < cnt) {
                    wb = __shfl_sync(0xffffffffu, p, i + 3);
                    int sn = __shfl_sync(0xffffffffu, s, i + 3);
                    vb = *(const uint4*)(g_xlh + (size_t)sn * 128 + lane * 4);
                }
                const __half2* h2 = (const __half2*)&v2;
                float2 f0 = __half22float2(h2[0]), f1 = __half22float2(h2[1]);
                float2 f2 = __half22float2(h2[2]), f3 = __half22float2(h2[3]);
                acc[0] += w2 * f0.x; acc[1] += w2 * f0.y;
                acc[2] += w2 * f1.x; acc[3] += w2 * f1.y;
                acc[4] += w2 * f2.x; acc[5] += w2 * f2.y;
                acc[6] += w2 * f3.x; acc[7] += w2 * f3.y;
            }
        }
    }
    // self loop
    {
        float wv = __expf(selfa - m);
        denom = warp_sum(denom) + wv;
        uint4 v = *(const uint4*)(g_xlh + (size_t)gw * 128 + lane * 4);
        const __half2* h2 = (const __half2*)&v;
        float2 f0 = __half22float2(h2[0]), f1 = __half22float2(h2[1]);
        float2 f2 = __half22float2(h2[2]), f3 = __half22float2(h2[3]);
        acc[0] += wv * f0.x; acc[1] += wv * f0.y;
        acc[2] += wv * f1.x; acc[3] += wv * f1.y;
        acc[4] += wv * f2.x; acc[5] += wv * f2.y;
        acc[6] += wv * f3.x; acc[7] += wv * f3.y;
    }
    float inv = 1.0f / denom;
    float* hrow = g_h + (size_t)gw * EMB + lane * 8;
    const float4* b4 = (const float4*)(bias + lane * 8);
    float4 b0 = b4[0], b1 = b4[1];
    float4 h0 = *(float4*)hrow, h1 = *(float4*)(hrow + 4);
    float r[8];
    r[0] = acc[0] * inv + b0.x; r[1] = acc[1] * inv + b0.y;
    r[2] = acc[2] * inv + b0.z; r[3] = acc[3] * inv + b0.w;
    r[4] = acc[4] * inv + b1.x; r[5] = acc[5] * inv + b1.y;
    r[6] = acc[6] * inv + b1.z; r[7] = acc[7] * inv + b1.w;
    if (do_relu) {
#pragma unroll
        for (int j = 0; j < 8; j++) r[j] = fmaxf(r[j], 0.f);
    }
    r[0] += h0.x; r[1] += h0.y; r[2] += h0.z; r[3] += h0.w;
    r[4] += h1.x; r[5] += h1.y; r[6] += h1.z; r[7] += h1.w;
    *(float4*)hrow = make_float4(r[0], r[1], r[2], r[3]);
    *(float4*)(hrow + 4) = make_float4(r[4], r[5], r[6], r[7]);
    // fp16 shadow for next layer's GEMM
    __half2 o[4];
    o[0] = __floats2half2_rn(r[0], r[1]);
    o[1] = __floats2half2_rn(r[2], r[3]);
    o[2] = __floats2half2_rn(r[4], r[5]);
    o[3] = __floats2half2_rn(r[6], r[7]);
    *(uint4*)(g_h16 + (size_t)gw * EMB + lane * 8) = *(uint4*)o;
}

// pooling: s[n] = h[n].wv, atomic into graph buckets
__global__ void k_pool(const int* __restrict__ batch) {
    int gw = (blockIdx.x * blockDim.x + threadIdx.x) >> 5;
    int lane = threadIdx.x & 31;
    if (gw >= NN) return;
    const float4* row = (const float4*)(g_h + (size_t)gw * EMB);
    const float4* w4 = (const float4*)g_wv;
    float4 v0 = row[lane], v1 = row[lane + 32];
    float4 w0 = w4[lane], w1 = w4[lane + 32];
    float s = v0.x * w0.x + v0.y * w0.y + v0.z * w0.z + v0.w * w0.w +
              v1.x * w1.x + v1.y * w1.y + v1.z * w1.z + v1.w * w1.w;
    s = warp_sum(s);
    if (lane == 0) {
        int g = batch[gw];
        atomicAdd(&g_gsum[g], s);
        atomicAdd(&g_gcnt[g], 1.0f);
    }
}

__global__ void k_final(float* __restrict__ out) {
    int g = blockIdx.x * blockDim.x + threadIdx.x;
    if (g < GG) out[g] = g_gsum[g] / fmaxf(g_gcnt[g], 1.0f) + g_bconst;
}

// ---------------- launch -----------------------------------------------------
extern "C" void kernel_launch(void* const* d_in, const int* in_sizes, int n_in,
                              void* d_out, int out_size) {
    const int* x = (const int*)d_in[0];
    const int* edge_index = (const int*)d_in[1];
    const int* edge_attr = (const int*)d_in[2];
    const int* batch = (const int*)d_in[3];
    const float* atom_emb = (const float*)d_in[4];
    const float* bond_emb = (const float*)d_in[5];
    const float* W = (const float*)d_in[6];
    const float* att_src = (const float*)d_in[7];
    const float* att_dst = (const float*)d_in[8];
    const float* We = (const float*)d_in[9];
    const float* att_edge = (const float*)d_in[10];
    const float* bias = (const float*)d_in[11];
    const float* W1 = (const float*)d_in[12];
    const float* b1 = (const float*)d_in[13];
    const float* W2 = (const float*)d_in[14];
    const float* b2 = (const float*)d_in[15];
    float* out = (float*)d_out;

    const int* src = edge_index;
    const int* dst = edge_index + EE;

    const int eblocks = (EE + 255) / 256;
    const int nwarp_blocks = (NN + 7) / 8;  // 8 warps per 256-thread block

    k_init<<<(NN + 255) / 256, 256>>>();
    k_atom<<<NN, 256>>>(x, atom_emb);
    k_wconv<<<dim3(8, 8, 3), dim3(32, 8)>>>(W);
    // layer-0 GEMM placed 4th so the ncu capture (4th launch) profiles it
    k_mma<<<dim3(NPAD / 128, EMB / 128), 256>>>(0);
    k_hist<<<eblocks, 256>>>(dst);
    k_scan_red<<<SCB, 1024>>>();
    k_scan_top<<<1, 32>>>();
    k_scan_low<<<SCB, 1024>>>();
    k_scatter<<<eblocks, 256>>>(src, dst, edge_attr);
    k_head<<<1, 256>>>(W1, b1, W2, b2);

    for (int l = 0; l < 3; l++) {
        k_lprep<<<1, 96>>>(We, att_edge, bond_emb, l);
        if (l > 0) k_mma<<<dim3(NPAD / 128, EMB / 128), 256>>>(l);
        k_asad<<<nwarp_blocks, 256>>>(att_src + l * EMB, att_dst + l * EMB);
        k_att<<<nwarp_blocks, 256>>>(bias + l * EMB, (l < 2) ? 1 : 0);
    }

    k_pool<<<nwarp_blocks, 256>>>(batch);
    k_final<<<2, 256>>>(out);
}

// round 6
// speedup vs baseline: 2.0093x; 1.0510x over previous
#include <cuda_runtime.h>
#include <cuda_fp16.h>
#include <math.h>

// Problem constants (fixed shapes for GAT_76184129896720)
#define NN 30000
#define NPAD 30080           // 235 * 128, padded for GEMM
#define EE 480000
#define EMB 256
#define GG 512
#define NEG_SLOPE 0.2f
#define SCB 30               // scan blocks (30*1024 >= NN)

// ---------------- device scratch (static; no allocations allowed) ----------
__device__ float   g_h[NPAD * EMB];    // node features (fp32, residual stream)
__device__ __half  g_h16[NPAD * EMB];  // fp16 shadow of h (GEMM A input)
__device__ __half  g_w16[3 * EMB * EMB]; // per-layer W, fp16, transposed [n][k]
__device__ __half2 g_xlh[NPAD * 128];  // h @ W[l] in fp16 (256 halves per row)
__device__ float   g_as[NN];
__device__ float   g_ad[NN];
__device__ int     g_deg[NN];
__device__ int     g_rowptr[NN + 1];
__device__ int     g_cursor[NN];
__device__ int     g_csr_src[EE];
__device__ unsigned g_csr_ea[EE];      // packed bond attrs a0|a1<<8|a2<<16
__device__ int     g_bsum[SCB];
__device__ int     g_boff[SCB];
__device__ float   g_dtable[3 * 48];   // per-layer 3 x 16 bond scalar LUT
__device__ float   g_wv[EMB];          // W1 @ W2
__device__ float   g_bconst;           // b1 @ W2 + b2
__device__ float   g_gsum[GG];
__device__ float   g_gcnt[GG];

// ---------------- helpers ---------------------------------------------------
__device__ __forceinline__ float warp_sum(float v) {
#pragma unroll
    for (int o = 16; o > 0; o >>= 1) v += __shfl_xor_sync(0xffffffffu, v, o);
    return v;
}
__device__ __forceinline__ int warp_sum_i(int v) {
#pragma unroll
    for (int o = 16; o > 0; o >>= 1) v += __shfl_xor_sync(0xffffffffu, v, o);
    return v;
}
__device__ __forceinline__ float warp_max(float v) {
#pragma unroll
    for (int o = 16; o > 0; o >>= 1) v = fmaxf(v, __shfl_xor_sync(0xffffffffu, v, o));
    return v;
}
__device__ __forceinline__ void cp16(unsigned dst, const void* src) {
    asm volatile("cp.async.cg.shared.global [%0], [%1], 16;" :: "r"(dst), "l"(src));
}
__device__ __forceinline__ void ldsm4(unsigned addr, unsigned& r0, unsigned& r1,
                                      unsigned& r2, unsigned& r3) {
    asm volatile("ldmatrix.sync.aligned.m8n8.x4.shared.b16 {%0,%1,%2,%3}, [%4];"
                 : "=r"(r0), "=r"(r1), "=r"(r2), "=r"(r3) : "r"(addr));
}
// smem tile layout: 2 logical rows per 128B physical row, XOR swizzle.
__device__ __forceinline__ int swoff(int m, int kc) {
    int p = m >> 1;
    int c = ((m & 1) << 2) | (kc ^ (p & 3));
    return p * 128 + c * 16;
}

// ---------------- setup kernels ---------------------------------------------

__global__ void k_init() {
    int i = blockIdx.x * blockDim.x + threadIdx.x;
    if (i < NN) { g_deg[i] = 0; g_cursor[i] = 0; }
    if (i < GG) { g_gsum[i] = 0.f; g_gcnt[i] = 0.f; }
    if (i < (NPAD - NN) * EMB) {
        g_h[NN * EMB + i] = 0.f;
        g_h16[NN * EMB + i] = __float2half(0.f);
    }
}

// AtomEncoder: h[n][c] = sum_i atom_emb[i][x[n,i]][c]  (+ fp16 shadow)
__global__ void k_atom(const int* __restrict__ x, const float* __restrict__ emb) {
    int n = blockIdx.x;
    int c = threadIdx.x;  // 256
    __shared__ int xi[9];
    if (c < 9) xi[c] = x[n * 9 + c];
    __syncthreads();
    float s = 0.f;
#pragma unroll
    for (int i = 0; i < 9; i++) s += emb[(i * 128 + xi[i]) * EMB + c];
    g_h[n * EMB + c] = s;
    g_h16[n * EMB + c] = __float2half(s);
}

// convert + transpose weights: g_w16[l][n][k] = fp16(W[l][k][n])
__global__ void k_wconv(const float* __restrict__ W) {
    __shared__ float tile[32][33];
    int l = blockIdx.z;
    int kb = blockIdx.x * 32, nb = blockIdx.y * 32;
    for (int i = threadIdx.y; i < 32; i += 8)
        tile[i][threadIdx.x] = W[(size_t)l * EMB * EMB + (kb + i) * EMB + nb + threadIdx.x];
    __syncthreads();
    for (int i = threadIdx.y; i < 32; i += 8)
        g_w16[(size_t)l * EMB * EMB + (nb + i) * EMB + kb + threadIdx.x] =
            __float2half(tile[threadIdx.x][i]);
}

__global__ void k_hist(const int* __restrict__ dst) {
    int e = blockIdx.x * blockDim.x + threadIdx.x;
    if (e < EE) atomicAdd(&g_deg[dst[e]], 1);
}

// --------- 3-phase multi-block exclusive scan of g_deg -> g_rowptr ----------
__global__ void k_scan_red() {
    __shared__ int ws[32];
    int t = threadIdx.x, lane = t & 31, wid = t >> 5;
    int idx = blockIdx.x * 1024 + t;
    int v = (idx < NN) ? g_deg[idx] : 0;
    v = warp_sum_i(v);
    if (lane == 0) ws[wid] = v;
    __syncthreads();
    if (wid == 0) {
        int s = ws[lane];
        s = warp_sum_i(s);
        if (lane == 0) g_bsum[blockIdx.x] = s;
    }
}
__global__ void k_scan_top() {
    int lane = threadIdx.x;
    int v = (lane < SCB) ? g_bsum[lane] : 0;
    int x = v;
#pragma unroll
    for (int o = 1; o < 32; o <<= 1) {
        int y = __shfl_up_sync(0xffffffffu, x, o);
        if (lane >= o) x += y;
    }
    if (lane < SCB) g_boff[lane] = x - v;
}
__global__ void k_scan_low() {
    __shared__ int ws[32];
    int t = threadIdx.x, lane = t & 31, wid = t >> 5;
    int idx = blockIdx.x * 1024 + t;
    int v = (idx < NN) ? g_deg[idx] : 0;
    int x = v;
#pragma unroll
    for (int o = 1; o < 32; o <<= 1) {
        int y = __shfl_up_sync(0xffffffffu, x, o);
        if (lane >= o) x += y;
    }
    if (lane == 31) ws[wid] = x;
    __syncthreads();
    if (wid == 0) {
        int w = ws[lane];
#pragma unroll
        for (int o = 1; o < 32; o <<= 1) {
            int y = __shfl_up_sync(0xffffffffu, w, o);
            if (lane >= o) w += y;
        }
        ws[lane] = w;
    }
    __syncthreads();
    int incl = x + ((wid > 0) ? ws[wid - 1] : 0) + g_boff[blockIdx.x];
    if (idx < NN) g_rowptr[idx + 1] = incl;
    if (idx == 0) g_rowptr[0] = 0;
}

__global__ void k_scatter(const int* __restrict__ src, const int* __restrict__ dst,
                          const int* __restrict__ ea) {
    int e = blockIdx.x * blockDim.x + threadIdx.x;
    if (e >= EE) return;
    int d = dst[e];
    int pos = g_rowptr[d] + atomicAdd(&g_cursor[d], 1);
    g_csr_src[pos] = src[e];
    g_csr_ea[pos] = (unsigned)ea[e * 3 + 0] | ((unsigned)ea[e * 3 + 1] << 8) |
                    ((unsigned)ea[e * 3 + 2] << 16);
}

// fused precompute: block 0 = head (wv, bconst); blocks 1..3 = lprep layer b-1
__global__ void k_prep(const float* __restrict__ W1, const float* __restrict__ b1,
                       const float* __restrict__ W2, const float* __restrict__ b2,
                       const float* __restrict__ We, const float* __restrict__ att_edge,
                       const float* __restrict__ bond_emb) {
    int t = threadIdx.x;  // 256
    if (blockIdx.x == 0) {
        int c = t;
        float acc = 0.f;
#pragma unroll 8
        for (int j = 0; j < EMB; j++) acc += W1[c * EMB + j] * W2[j];
        g_wv[c] = acc;
        __shared__ float sh[EMB];
        sh[c] = b1[c] * W2[c];
        __syncthreads();
        for (int s = 128; s > 0; s >>= 1) {
            if (c < s) sh[c] += sh[c + s];
            __syncthreads();
        }
        if (c == 0) g_bconst = sh[0] + b2[0];
    } else {
        int l = blockIdx.x - 1;
        __shared__ float wa[3];
        int w = t >> 5, lane = t & 31;
        if (w < 3) {
            float p = 0.f;
            for (int k = lane; k < EMB; k += 32)
                p += We[(l * 3 + w) * EMB + k] * att_edge[l * EMB + k];
            p = warp_sum(p);
            if (lane == 0) wa[w] = p;
        }
        __syncthreads();
        if (t < 48) {
            int j = t >> 4, v = t & 15;
            const float* be = bond_emb + ((size_t)(l * 3 + j) * 16 + v) * 3;
            g_dtable[l * 48 + t] = be[0] * wa[0] + be[1] * wa[1] + be[2] * wa[2];
        }
    }
}

// ------- fp16 GEMM: g_xlh = fp16(g_h16 @ g_w16[l]^T-layout), cp.async+ldmatrix
// Block 128x128, K slab 32, 3-stage pipeline, 8 warps (2x4), warp tile 64x32.
// __launch_bounds__(256, 2): cap regs at 128 -> 2 CTAs/SM (occupancy fix)
__global__ __launch_bounds__(256, 2) void k_mma(int l) {
    __shared__ __align__(16) char sm[49152];  // 3 stages x (A 8KB + B 8KB)
    const unsigned smb = (unsigned)__cvta_generic_to_shared(sm);
    const int tid = threadIdx.x;
    const int lane = tid & 31;
    const int w = tid >> 5;
    const int tig = lane & 3, gid = lane >> 2;
    const int warp_m = w >> 2, warp_n = w & 3;
    const int r0 = blockIdx.x * 128, c0 = blockIdx.y * 128;

    const int lm = tid & 127;
    const int lkc = (tid >> 7) * 2;  // chunk base 0 or 2
    const __half* Ag = g_h16 + (size_t)(r0 + lm) * EMB + lkc * 8;
    const __half* Bg = g_w16 + (size_t)l * EMB * EMB + (size_t)(c0 + lm) * EMB + lkc * 8;
    const int sA0 = swoff(lm, lkc), sA1 = swoff(lm, lkc + 1);

    float acc[16][4];
#pragma unroll
    for (int i = 0; i < 16; i++)
#pragma unroll
        for (int j = 0; j < 4; j++) acc[i][j] = 0.f;

#define ISSUE(s)                                                          \
    {                                                                     \
        unsigned st = smb + ((s) % 3) * 16384;                            \
        cp16(st + sA0, Ag + (s) * 32);                                    \
        cp16(st + sA1, Ag + (s) * 32 + 8);                                \
        cp16(st + 8192 + sA0, Bg + (s) * 32);                             \
        cp16(st + 8192 + sA1, Bg + (s) * 32 + 8);                         \
        asm volatile("cp.async.commit_group;");                           \
    }

    ISSUE(0);
    ISSUE(1);

#pragma unroll
    for (int s = 0; s < 8; s++) {
        if (s < 7) asm volatile("cp.async.wait_group 1;");
        else       asm volatile("cp.async.wait_group 0;");
        __syncthreads();
        if (s + 2 < 8) ISSUE(s + 2);
        unsigned Ab = smb + (s % 3) * 16384;
        unsigned Bb = Ab + 8192;
#pragma unroll
        for (int kk = 0; kk < 32; kk += 16) {
            unsigned af[4][4], bf[4][2];
#pragma unroll
            for (int mt = 0; mt < 4; mt++) {
                int r = warp_m * 64 + mt * 16 + (lane & 15);
                int kc = (kk >> 3) + (lane >> 4);
                ldsm4(Ab + swoff(r, kc), af[mt][0], af[mt][1], af[mt][2], af[mt][3]);
            }
#pragma unroll
            for (int pr = 0; pr < 2; pr++) {
                int n = warp_n * 32 + pr * 16 + ((lane >> 4) & 1) * 8 + (lane & 7);
                int kc = (kk >> 3) + ((lane >> 3) & 1);
                ldsm4(Bb + swoff(n, kc), bf[2 * pr][0], bf[2 * pr][1],
                      bf[2 * pr + 1][0], bf[2 * pr + 1][1]);
            }
#pragma unroll
            for (int mt = 0; mt < 4; mt++)
#pragma unroll
                for (int nt = 0; nt < 4; nt++) {
                    float* c = acc[mt * 4 + nt];
                    asm volatile(
                        "mma.sync.aligned.m16n8k16.row.col.f32.f16.f16.f32 "
                        "{%0,%1,%2,%3}, {%4,%5,%6,%7}, {%8,%9}, {%0,%1,%2,%3};"
                        : "+f"(c[0]), "+f"(c[1]), "+f"(c[2]), "+f"(c[3])
                        : "r"(af[mt][0]), "r"(af[mt][1]), "r"(af[mt][2]), "r"(af[mt][3]),
                          "r"(bf[nt][0]), "r"(bf[nt][1]));
                }
        }
    }
#undef ISSUE
#pragma unroll
    for (int mt = 0; mt < 4; mt++) {
        int r = r0 + warp_m * 64 + mt * 16 + gid;
#pragma unroll
        for (int nt = 0; nt < 4; nt++) {
            int ch = (c0 + warp_n * 32 + nt * 8 + 2 * tig) >> 1;
            const float* a = acc[mt * 4 + nt];
            g_xlh[(size_t)r * 128 + ch] = __floats2half2_rn(a[0], a[1]);
            g_xlh[(size_t)(r + 8) * 128 + ch] = __floats2half2_rn(a[2], a[3]);
        }
    }
}

// as[n] = xl[n].att_src ; ad[n] = xl[n].att_dst  (warp per node, fp16 xl)
__global__ void k_asad(const float* __restrict__ att_s, const float* __restrict__ att_d) {
    int gw = (blockIdx.x * blockDim.x + threadIdx.x) >> 5;
    int lane = threadIdx.x & 31;
    if (gw >= NN) return;
    uint4 v = *(const uint4*)(g_xlh + (size_t)gw * 128 + lane * 4);
    const __half2* h2 = (const __half2*)&v;
    float2 f0 = __half22float2(h2[0]), f1 = __half22float2(h2[1]);
    float2 f2 = __half22float2(h2[2]), f3 = __half22float2(h2[3]);
    const float4* s4 = (const float4*)(att_s + lane * 8);
    const float4* d4 = (const float4*)(att_d + lane * 8);
    float4 s0 = s4[0], s1 = s4[1];
    float4 dd0 = d4[0], dd1 = d4[1];
    float ss = f0.x * s0.x + f0.y * s0.y + f1.x * s0.z + f1.y * s0.w +
               f2.x * s1.x + f2.y * s1.y + f3.x * s1.z + f3.y * s1.w;
    float dd = f0.x * dd0.x + f0.y * dd0.y + f1.x * dd0.z + f1.y * dd0.w +
               f2.x * dd1.x + f2.y * dd1.y + f3.x * dd1.z + f3.y * dd1.w;
    ss = warp_sum(ss);
    dd = warp_sum(dd);
    if (lane == 0) { g_as[gw] = ss; g_ad[gw] = dd; }
}

// fused attention: softmax + weighted gather + bias/relu/residual (warp per node)
__global__ void k_att(const float* __restrict__ bias, int do_relu, int l) {
    int gw = (blockIdx.x * blockDim.x + threadIdx.x) >> 5;
    int lane = threadIdx.x & 31;
    if (gw >= NN) return;
    const float* dt = g_dtable + l * 48;
    int start = g_rowptr[gw], end = g_rowptr[gw + 1];
    float adn = g_ad[gw];

    // pass A: max + edot sum (for self loop)
    float mx = -1e30f, esum = 0.f;
    for (int pos = start + lane; pos < end; pos += 32) {
        unsigned ea = g_csr_ea[pos];
        float ed = dt[ea & 15] + dt[16 + ((ea >> 8) & 15)] + dt[32 + ((ea >> 16) & 15)];
        float a = g_as[g_csr_src[pos]] + adn + ed;
        a = (a >= 0.f) ? a : NEG_SLOPE * a;
        mx = fmaxf(mx, a);
        esum += ed;
    }
    mx = warp_max(mx);
    esum = warp_sum(esum);
    int deg = end - start;
    float selfa = g_as[gw] + adn + esum / fmaxf((float)deg, 1.0f);
    selfa = (selfa >= 0.f) ? selfa : NEG_SLOPE * selfa;
    float m = fmaxf(mx, selfa);

    // pass B: exp weights + weighted row gather, depth-2 pipelined
    float acc[8] = {0, 0, 0, 0, 0, 0, 0, 0};
    float denom = 0.f;
    for (int cb = start; cb < end; cb += 32) {
        int pos = cb + lane;
        float p = 0.f;
        int s = 0;
        if (pos < end) {
            unsigned ea = g_csr_ea[pos];
            float ed = dt[ea & 15] + dt[16 + ((ea >> 8) & 15)] + dt[32 + ((ea >> 16) & 15)];
            s = g_csr_src[pos];
            float a = g_as[s] + adn + ed;
            a = (a >= 0.f) ? a : NEG_SLOPE * a;
            p = __expf(a - m);
        }
        denom += p;
        int cnt = min(32, end - cb);
        uint4 va = make_uint4(0, 0, 0, 0), vb = make_uint4(0, 0, 0, 0);
        float wa = 0.f, wb = 0.f;
        if (cnt > 0) {
            wa = __shfl_sync(0xffffffffu, p, 0);
            int s0 = __shfl_sync(0xffffffffu, s, 0);
            va = *(const uint4*)(g_xlh + (size_t)s0 * 128 + lane * 4);
        }
        if (cnt > 1) {
            wb = __shfl_sync(0xffffffffu, p, 1);
            int s1 = __shfl_sync(0xffffffffu, s, 1);
            vb = *(const uint4*)(g_xlh + (size_t)s1 * 128 + lane * 4);
        }
        for (int i = 0; i < cnt; i += 2) {
            uint4 v = va;
            float wv = wa;
            if (i + 2 < cnt) {
                wa = __shfl_sync(0xffffffffu, p, i + 2);
                int sn = __shfl_sync(0xffffffffu, s, i + 2);
                va = *(const uint4*)(g_xlh + (size_t)sn * 128 + lane * 4);
            }
            {
                const __half2* h2 = (const __half2*)&v;
                float2 f0 = __half22float2(h2[0]), f1 = __half22float2(h2[1]);
                float2 f2 = __half22float2(h2[2]), f3 = __half22float2(h2[3]);
                acc[0] += wv * f0.x; acc[1] += wv * f0.y;
                acc[2] += wv * f1.x; acc[3] += wv * f1.y;
                acc[4] += wv * f2.x; acc[5] += wv * f2.y;
                acc[6] += wv * f3.x; acc[7] += wv * f3.y;
            }
            if (i + 1 < cnt) {
                uint4 v2 = vb;
                float w2 = wb;
                if (i + 3 < cnt) {
                    wb = __shfl_sync(0xffffffffu, p, i + 3);
                    int sn = __shfl_sync(0xffffffffu, s, i + 3);
                    vb = *(const uint4*)(g_xlh + (size_t)sn * 128 + lane * 4);
                }
                const __half2* h2 = (const __half2*)&v2;
                float2 f0 = __half22float2(h2[0]), f1 = __half22float2(h2[1]);
                float2 f2 = __half22float2(h2[2]), f3 = __half22float2(h2[3]);
                acc[0] += w2 * f0.x; acc[1] += w2 * f0.y;
                acc[2] += w2 * f1.x; acc[3] += w2 * f1.y;
                acc[4] += w2 * f2.x; acc[5] += w2 * f2.y;
                acc[6] += w2 * f3.x; acc[7] += w2 * f3.y;
            }
        }
    }
    // self loop
    {
        float wv = __expf(selfa - m);
        denom = warp_sum(denom) + wv;
        uint4 v = *(const uint4*)(g_xlh + (size_t)gw * 128 + lane * 4);
        const __half2* h2 = (const __half2*)&v;
        float2 f0 = __half22float2(h2[0]), f1 = __half22float2(h2[1]);
        float2 f2 = __half22float2(h2[2]), f3 = __half22float2(h2[3]);
        acc[0] += wv * f0.x; acc[1] += wv * f0.y;
        acc[2] += wv * f1.x; acc[3] += wv * f1.y;
        acc[4] += wv * f2.x; acc[5] += wv * f2.y;
        acc[6] += wv * f3.x; acc[7] += wv * f3.y;
    }
    float inv = 1.0f / denom;
    float* hrow = g_h + (size_t)gw * EMB + lane * 8;
    const float4* b4 = (const float4*)(bias + lane * 8);
    float4 b0 = b4[0], b1 = b4[1];
    float4 h0 = *(float4*)hrow, h1 = *(float4*)(hrow + 4);
    float r[8];
    r[0] = acc[0] * inv + b0.x; r[1] = acc[1] * inv + b0.y;
    r[2] = acc[2] * inv + b0.z; r[3] = acc[3] * inv + b0.w;
    r[4] = acc[4] * inv + b1.x; r[5] = acc[5] * inv + b1.y;
    r[6] = acc[6] * inv + b1.z; r[7] = acc[7] * inv + b1.w;
    if (do_relu) {
#pragma unroll
        for (int j = 0; j < 8; j++) r[j] = fmaxf(r[j], 0.f);
    }
    r[0] += h0.x; r[1] += h0.y; r[2] += h0.z; r[3] += h0.w;
    r[4] += h1.x; r[5] += h1.y; r[6] += h1.z; r[7] += h1.w;
    *(float4*)hrow = make_float4(r[0], r[1], r[2], r[3]);
    *(float4*)(hrow + 4) = make_float4(r[4], r[5], r[6], r[7]);
    // fp16 shadow for next layer's GEMM
    __half2 o[4];
    o[0] = __floats2half2_rn(r[0], r[1]);
    o[1] = __floats2half2_rn(r[2], r[3]);
    o[2] = __floats2half2_rn(r[4], r[5]);
    o[3] = __floats2half2_rn(r[6], r[7]);
    *(uint4*)(g_h16 + (size_t)gw * EMB + lane * 8) = *(uint4*)o;
}

// pooling: s[n] = h[n].wv, atomic into graph buckets
__global__ void k_pool(const int* __restrict__ batch) {
    int gw = (blockIdx.x * blockDim.x + threadIdx.x) >> 5;
    int lane = threadIdx.x & 31;
    if (gw >= NN) return;
    const float4* row = (const float4*)(g_h + (size_t)gw * EMB);
    const float4* w4 = (const float4*)g_wv;
    float4 v0 = row[lane], v1 = row[lane + 32];
    float4 w0 = w4[lane], w1 = w4[lane + 32];
    float s = v0.x * w0.x + v0.y * w0.y + v0.z * w0.z + v0.w * w0.w +
              v1.x * w1.x + v1.y * w1.y + v1.z * w1.z + v1.w * w1.w;
    s = warp_sum(s);
    if (lane == 0) {
        int g = batch[gw];
        atomicAdd(&g_gsum[g], s);
        atomicAdd(&g_gcnt[g], 1.0f);
    }
}

__global__ void k_final(float* __restrict__ out) {
    int g = blockIdx.x * blockDim.x + threadIdx.x;
    if (g < GG) out[g] = g_gsum[g] / fmaxf(g_gcnt[g], 1.0f) + g_bconst;
}

// ---------------- launch -----------------------------------------------------
extern "C" void kernel_launch(void* const* d_in, const int* in_sizes, int n_in,
                              void* d_out, int out_size) {
    const int* x = (const int*)d_in[0];
    const int* edge_index = (const int*)d_in[1];
    const int* edge_attr = (const int*)d_in[2];
    const int* batch = (const int*)d_in[3];
    const float* atom_emb = (const float*)d_in[4];
    const float* bond_emb = (const float*)d_in[5];
    const float* W = (const float*)d_in[6];
    const float* att_src = (const float*)d_in[7];
    const float* att_dst = (const float*)d_in[8];
    const float* We = (const float*)d_in[9];
    const float* att_edge = (const float*)d_in[10];
    const float* bias = (const float*)d_in[11];
    const float* W1 = (const float*)d_in[12];
    const float* b1 = (const float*)d_in[13];
    const float* W2 = (const float*)d_in[14];
    const float* b2 = (const float*)d_in[15];
    float* out = (float*)d_out;

    const int* src = edge_index;
    const int* dst = edge_index + EE;

    const int eblocks = (EE + 255) / 256;
    const int nwarp_blocks = (NN + 7) / 8;  // 8 warps per 256-thread block

    k_init<<<(NN + 255) / 256, 256>>>();
    k_atom<<<NN, 256>>>(x, atom_emb);
    k_wconv<<<dim3(8, 8, 3), dim3(32, 8)>>>(W);
    // layer-0 GEMM placed 4th so the ncu capture (4th launch) profiles it
    k_mma<<<dim3(NPAD / 128, EMB / 128), 256>>>(0);
    k_hist<<<eblocks, 256>>>(dst);
    k_scan_red<<<SCB, 1024>>>();
    k_scan_top<<<1, 32>>>();
    k_scan_low<<<SCB, 1024>>>();
    k_scatter<<<eblocks, 256>>>(src, dst, edge_attr);
    k_prep<<<4, 256>>>(W1, b1, W2, b2, We, att_edge, bond_emb);

    for (int l = 0; l < 3; l++) {
        if (l > 0) k_mma<<<dim3(NPAD / 128, EMB / 128), 256>>>(l);
        k_asad<<<nwarp_blocks, 256>>>(att_src + l * EMB, att_dst + l * EMB);
        k_att<<<nwarp_blocks, 256>>>(bias + l * EMB, (l < 2) ? 1 : 0, l);
    }

    k_pool<<<nwarp_blocks, 256>>>(batch);
    k_final<<<2, 256>>>(out);
}

// round 8
// speedup vs baseline: 2.0875x; 1.0389x over previous
#include <cuda_runtime.h>
#include <cuda_fp16.h>
#include <math.h>

// Problem constants (fixed shapes for GAT_76184129896720)
#define NN 30000
#define NPAD 30080           // 235 * 128
#define EE 480000
#define EMB 256
#define GG 512
#define NEG_SLOPE 0.2f
#define SCB 30

// ---------------- device scratch (static; no allocations allowed) ----------
__device__ float   g_h[NPAD * EMB];    // node features (fp32, residual stream)
__device__ __half  g_h16[NPAD * EMB];  // fp16 shadow of h (GEMM A input)
__device__ __half  g_w16[3 * EMB * EMB]; // per-layer W, fp16, transposed [n][k]
__device__ __half  g_emb16[9 * 128 * EMB]; // fp16 atom embedding tables
__device__ __half2 g_xlh[NPAD * 128];  // h @ W[l] in fp16 (256 halves per row)
__device__ float   g_asL[3 * NN];      // per-layer xl.att_src (epilogue-fused)
__device__ float   g_adL[3 * NN];      // per-layer xl.att_dst
__device__ int     g_deg[NN];
__device__ int     g_rowptr[NN + 1];
__device__ int     g_cursor[NN];
__device__ int     g_csr_src[EE];
__device__ unsigned g_csr_ea[EE];      // packed bond attrs
__device__ int     g_bsum[SCB];
__device__ int     g_boff[SCB];
__device__ float   g_dtable[3 * 48];
__device__ float   g_wv[EMB];
__device__ float   g_bconst;
__device__ float   g_gsum[GG];
__device__ float   g_gcnt[GG];

// ---------------- helpers ---------------------------------------------------
__device__ __forceinline__ float warp_sum(float v) {
#pragma unroll
    for (int o = 16; o > 0; o >>= 1) v += __shfl_xor_sync(0xffffffffu, v, o);
    return v;
}
__device__ __forceinline__ int warp_sum_i(int v) {
#pragma unroll
    for (int o = 16; o > 0; o >>= 1) v += __shfl_xor_sync(0xffffffffu, v, o);
    return v;
}
__device__ __forceinline__ float warp_max(float v) {
#pragma unroll
    for (int o = 16; o > 0; o >>= 1) v = fmaxf(v, __shfl_xor_sync(0xffffffffu, v, o));
    return v;
}
__device__ __forceinline__ void cp16(unsigned dst, const void* src) {
    asm volatile("cp.async.cg.shared.global [%0], [%1], 16;" :: "r"(dst), "l"(src));
}
__device__ __forceinline__ void ldsm4(unsigned addr, unsigned& r0, unsigned& r1,
                                      unsigned& r2, unsigned& r3) {
    asm volatile("ldmatrix.sync.aligned.m8n8.x4.shared.b16 {%0,%1,%2,%3}, [%4];"
                 : "=r"(r0), "=r"(r1), "=r"(r2), "=r"(r3) : "r"(addr));
}
// smem tile layout: 2 logical rows per 128B physical row, XOR swizzle.
__device__ __forceinline__ int swoff(int m, int kc) {
    int p = m >> 1;
    int c = ((m & 1) << 2) | (kc ^ (p & 3));
    return p * 128 + c * 16;
}

// ---------------- setup kernels ---------------------------------------------

__global__ void k_init() {
    int i = blockIdx.x * blockDim.x + threadIdx.x;
    if (i < NN) { g_deg[i] = 0; g_cursor[i] = 0; }
    if (i < GG) { g_gsum[i] = 0.f; g_gcnt[i] = 0.f; }
    if (i < (NPAD - NN) * EMB) {
        g_h[NN * EMB + i] = 0.f;
        g_h16[NN * EMB + i] = __float2half(0.f);
    }
    if (i < 3 * NN) { g_asL[i] = 0.f; g_adL[i] = 0.f; }
}

// convert+transpose weights AND convert atom-embedding tables to fp16
__global__ void k_wconv(const float* __restrict__ W, const float* __restrict__ emb) {
    __shared__ float tile[32][33];
    int l = blockIdx.z;
    int kb = blockIdx.x * 32, nb = blockIdx.y * 32;
    for (int i = threadIdx.y; i < 32; i += 8)
        tile[i][threadIdx.x] = W[(size_t)l * EMB * EMB + (kb + i) * EMB + nb + threadIdx.x];
    __syncthreads();
    for (int i = threadIdx.y; i < 32; i += 8)
        g_w16[(size_t)l * EMB * EMB + (nb + i) * EMB + kb + threadIdx.x] =
            __float2half(tile[threadIdx.x][i]);
    // emb conversion: 294912 elems over 192 blocks = 1536/block
    int t = threadIdx.y * 32 + threadIdx.x;               // 0..255
    int bid = (blockIdx.z * 8 + blockIdx.y) * 8 + blockIdx.x;  // 0..191
    int base = bid * 1536;
#pragma unroll
    for (int j = 0; j < 6; j++) {
        int idx = base + j * 256 + t;
        g_emb16[idx] = __float2half(emb[idx]);
    }
}

// AtomEncoder from fp16 tables: h[n][c] = sum_i emb16[i][x[n,i]][c]
__global__ void k_atom(const int* __restrict__ x) {
    int n = blockIdx.x;
    int c = threadIdx.x;  // 256
    __shared__ int xi[9];
    if (c < 9) xi[c] = x[n * 9 + c];
    __syncthreads();
    float s = 0.f;
#pragma unroll
    for (int i = 0; i < 9; i++)
        s += __half2float(g_emb16[(i * 128 + xi[i]) * EMB + c]);
    g_h[n * EMB + c] = s;
    g_h16[n * EMB + c] = __float2half(s);
}

__global__ void k_hist(const int* __restrict__ dst) {
    int e = blockIdx.x * blockDim.x + threadIdx.x;
    if (e < EE) atomicAdd(&g_deg[dst[e]], 1);
}

// --------- 3-phase multi-block exclusive scan of g_deg -> g_rowptr ----------
__global__ void k_scan_red() {
    __shared__ int ws[32];
    int t = threadIdx.x, lane = t & 31, wid = t >> 5;
    int idx = blockIdx.x * 1024 + t;
    int v = (idx < NN) ? g_deg[idx] : 0;
    v = warp_sum_i(v);
    if (lane == 0) ws[wid] = v;
    __syncthreads();
    if (wid == 0) {
        int s = ws[lane];
        s = warp_sum_i(s);
        if (lane == 0) g_bsum[blockIdx.x] = s;
    }
}
__global__ void k_scan_top() {
    int lane = threadIdx.x;
    int v = (lane < SCB) ? g_bsum[lane] : 0;
    int x = v;
#pragma unroll
    for (int o = 1; o < 32; o <<= 1) {
        int y = __shfl_up_sync(0xffffffffu, x, o);
        if (lane >= o) x += y;
    }
    if (lane < SCB) g_boff[lane] = x - v;
}
__global__ void k_scan_low() {
    __shared__ int ws[32];
    int t = threadIdx.x, lane = t & 31, wid = t >> 5;
    int idx = blockIdx.x * 1024 + t;
    int v = (idx < NN) ? g_deg[idx] : 0;
    int x = v;
#pragma unroll
    for (int o = 1; o < 32; o <<= 1) {
        int y = __shfl_up_sync(0xffffffffu, x, o);
        if (lane >= o) x += y;
    }
    if (lane == 31) ws[wid] = x;
    __syncthreads();
    if (wid == 0) {
        int w = ws[lane];
#pragma unroll
        for (int o = 1; o < 32; o <<= 1) {
            int y = __shfl_up_sync(0xffffffffu, w, o);
            if (lane >= o) w += y;
        }
        ws[lane] = w;
    }
    __syncthreads();
    int incl = x + ((wid > 0) ? ws[wid - 1] : 0) + g_boff[blockIdx.x];
    if (idx < NN) g_rowptr[idx + 1] = incl;
    if (idx == 0) g_rowptr[0] = 0;
}

__global__ void k_scatter(const int* __restrict__ src, const int* __restrict__ dst,
                          const int* __restrict__ ea) {
    int e = blockIdx.x * blockDim.x + threadIdx.x;
    if (e >= EE) return;
    int d = dst[e];
    int pos = g_rowptr[d] + atomicAdd(&g_cursor[d], 1);
    g_csr_src[pos] = src[e];
    g_csr_ea[pos] = (unsigned)ea[e * 3 + 0] | ((unsigned)ea[e * 3 + 1] << 8) |
                    ((unsigned)ea[e * 3 + 2] << 16);
}

// fused precompute: block 0 = head (wv, bconst); blocks 1..3 = lprep layer b-1
__global__ void k_prep(const float* __restrict__ W1, const float* __restrict__ b1,
                       const float* __restrict__ W2, const float* __restrict__ b2,
                       const float* __restrict__ We, const float* __restrict__ att_edge,
                       const float* __restrict__ bond_emb) {
    int t = threadIdx.x;  // 256
    if (blockIdx.x == 0) {
        int c = t;
        float acc = 0.f;
#pragma unroll 8
        for (int j = 0; j < EMB; j++) acc += W1[c * EMB + j] * W2[j];
        g_wv[c] = acc;
        __shared__ float sh[EMB];
        sh[c] = b1[c] * W2[c];
        __syncthreads();
        for (int s = 128; s > 0; s >>= 1) {
            if (c < s) sh[c] += sh[c + s];
            __syncthreads();
        }
        if (c == 0) g_bconst = sh[0] + b2[0];
    } else {
        int l = blockIdx.x - 1;
        __shared__ float wa[3];
        int w = t >> 5, lane = t & 31;
        if (w < 3) {
            float p = 0.f;
            for (int k = lane; k < EMB; k += 32)
                p += We[(l * 3 + w) * EMB + k] * att_edge[l * EMB + k];
            p = warp_sum(p);
            if (lane == 0) wa[w] = p;
        }
        __syncthreads();
        if (t < 48) {
            int j = t >> 4, v = t & 15;
            const float* be = bond_emb + ((size_t)(l * 3 + j) * 16 + v) * 3;
            g_dtable[l * 48 + t] = be[0] * wa[0] + be[1] * wa[1] + be[2] * wa[2];
        }
    }
}

// ------- fp16 GEMM + fused as/ad epilogue -----------------------------------
// Block 128x128, K slab 32, 3-stage cp.async pipeline, 8 warps (2x4).
__global__ __launch_bounds__(256, 2) void k_mma(int l, const float* __restrict__ att_s,
                                                const float* __restrict__ att_d) {
    __shared__ __align__(16) char sm[49152];
    const unsigned smb = (unsigned)__cvta_generic_to_shared(sm);
    const int tid = threadIdx.x;
    const int lane = tid & 31;
    const int w = tid >> 5;
    const int tig = lane & 3, gid = lane >> 2;
    const int warp_m = w >> 2, warp_n = w & 3;
    const int r0 = blockIdx.x * 128, c0 = blockIdx.y * 128;

    const int lm = tid & 127;
    const int lkc = (tid >> 7) * 2;
    const __half* Ag = g_h16 + (size_t)(r0 + lm) * EMB + lkc * 8;
    const __half* Bg = g_w16 + (size_t)l * EMB * EMB + (size_t)(c0 + lm) * EMB + lkc * 8;
    const int sA0 = swoff(lm, lkc), sA1 = swoff(lm, lkc + 1);

    float acc[16][4];
#pragma unroll
    for (int i = 0; i < 16; i++)
#pragma unroll
        for (int j = 0; j < 4; j++) acc[i][j] = 0.f;

#define ISSUE(s)                                                          \
    {                                                                     \
        unsigned st = smb + ((s) % 3) * 16384;                            \
        cp16(st + sA0, Ag + (s) * 32);                                    \
        cp16(st + sA1, Ag + (s) * 32 + 8);                                \
        cp16(st + 8192 + sA0, Bg + (s) * 32);                             \
        cp16(st + 8192 + sA1, Bg + (s) * 32 + 8);                         \
        asm volatile("cp.async.commit_group;");                           \
    }

    ISSUE(0);
    ISSUE(1);

#pragma unroll
    for (int s = 0; s < 8; s++) {
        if (s < 7) asm volatile("cp.async.wait_group 1;");
        else       asm volatile("cp.async.wait_group 0;");
        __syncthreads();
        if (s + 2 < 8) ISSUE(s + 2);
        unsigned Ab = smb + (s % 3) * 16384;
        unsigned Bb = Ab + 8192;
#pragma unroll
        for (int kk = 0; kk < 32; kk += 16) {
            unsigned af[4][4], bf[4][2];
#pragma unroll
            for (int mt = 0; mt < 4; mt++) {
                int r = warp_m * 64 + mt * 16 + (lane & 15);
                int kc = (kk >> 3) + (lane >> 4);
                ldsm4(Ab + swoff(r, kc), af[mt][0], af[mt][1], af[mt][2], af[mt][3]);
            }
#pragma unroll
            for (int pr = 0; pr < 2; pr++) {
                int n = warp_n * 32 + pr * 16 + ((lane >> 4) & 1) * 8 + (lane & 7);
                int kc = (kk >> 3) + ((lane >> 3) & 1);
                ldsm4(Bb + swoff(n, kc), bf[2 * pr][0], bf[2 * pr][1],
                      bf[2 * pr + 1][0], bf[2 * pr + 1][1]);
            }
#pragma unroll
            for (int mt = 0; mt < 4; mt++)
#pragma unroll
                for (int nt = 0; nt < 4; nt++) {
                    float* c = acc[mt * 4 + nt];
                    asm volatile(
                        "mma.sync.aligned.m16n8k16.row.col.f32.f16.f16.f32 "
                        "{%0,%1,%2,%3}, {%4,%5,%6,%7}, {%8,%9}, {%0,%1,%2,%3};"
                        : "+f"(c[0]), "+f"(c[1]), "+f"(c[2]), "+f"(c[3])
                        : "r"(af[mt][0]), "r"(af[mt][1]), "r"(af[mt][2]), "r"(af[mt][3]),
                          "r"(bf[nt][0]), "r"(bf[nt][1]));
                }
        }
    }
#undef ISSUE
    // epilogue: store fp16 xl + fused as/ad partial dots
    float* asbuf = g_asL + l * NN;
    float* adbuf = g_adL + l * NN;
#pragma unroll
    for (int mt = 0; mt < 4; mt++) {
        int r = r0 + warp_m * 64 + mt * 16 + gid;
        float ps = 0.f, pd = 0.f, qs = 0.f, qd = 0.f;
#pragma unroll
        for (int nt = 0; nt < 4; nt++) {
            int c = c0 + warp_n * 32 + nt * 8 + 2 * tig;
            int ch = c >> 1;
            const float* a = acc[mt * 4 + nt];
            g_xlh[(size_t)r * 128 + ch] = __floats2half2_rn(a[0], a[1]);
            g_xlh[(size_t)(r + 8) * 128 + ch] = __floats2half2_rn(a[2], a[3]);
            float s0 = att_s[c], s1 = att_s[c + 1];
            float d0 = att_d[c], d1 = att_d[c + 1];
            ps += a[0] * s0 + a[1] * s1;
            pd += a[0] * d0 + a[1] * d1;
            qs += a[2] * s0 + a[3] * s1;
            qd += a[2] * d0 + a[3] * d1;
        }
#pragma unroll
        for (int o = 1; o <= 2; o <<= 1) {
            ps += __shfl_xor_sync(0xffffffffu, ps, o);
            pd += __shfl_xor_sync(0xffffffffu, pd, o);
            qs += __shfl_xor_sync(0xffffffffu, qs, o);
            qd += __shfl_xor_sync(0xffffffffu, qd, o);
        }
        if (tig == 0) {
            if (r < NN) { atomicAdd(asbuf + r, ps); atomicAdd(adbuf + r, pd); }
            if (r + 8 < NN) { atomicAdd(asbuf + r + 8, qs); atomicAdd(adbuf + r + 8, qd); }
        }
    }
}

// fused attention: softmax + weighted gather + bias/relu/residual (warp per node)
__global__ void k_att(const float* __restrict__ bias, int do_relu, int l) {
    int gw = (blockIdx.x * blockDim.x + threadIdx.x) >> 5;
    int lane = threadIdx.x & 31;
    if (gw >= NN) return;
    const float* dt = g_dtable + l * 48;
    const float* asv = g_asL + l * NN;
    const float* adv = g_adL + l * NN;
    int start = g_rowptr[gw], end = g_rowptr[gw + 1];
    float adn = adv[gw];

    float mx = -1e30f, esum = 0.f;
    for (int pos = start + lane; pos < end; pos += 32) {
        unsigned ea = g_csr_ea[pos];
        float ed = dt[ea & 15] + dt[16 + ((ea >> 8) & 15)] + dt[32 + ((ea >> 16) & 15)];
        float a = asv[g_csr_src[pos]] + adn + ed;
        a = (a >= 0.f) ? a : NEG_SLOPE * a;
        mx = fmaxf(mx, a);
        esum += ed;
    }
    mx = warp_max(mx);
    esum = warp_sum(esum);
    int deg = end - start;
    float selfa = asv[gw] + adn + esum / fmaxf((float)deg, 1.0f);
    selfa = (selfa >= 0.f) ? selfa : NEG_SLOPE * selfa;
    float m = fmaxf(mx, selfa);

    float acc[8] = {0, 0, 0, 0, 0, 0, 0, 0};
    float denom = 0.f;
    for (int cb = start; cb < end; cb += 32) {
        int pos = cb + lane;
        float p = 0.f;
        int s = 0;
        if (pos < end) {
            unsigned ea = g_csr_ea[pos];
            float ed = dt[ea & 15] + dt[16 + ((ea >> 8) & 15)] + dt[32 + ((ea >> 16) & 15)];
            s = g_csr_src[pos];
            float a = asv[s] + adn + ed;
            a = (a >= 0.f) ? a : NEG_SLOPE * a;
            p = __expf(a - m);
        }
        denom += p;
        int cnt = min(32, end - cb);
        uint4 va = make_uint4(0, 0, 0, 0), vb = make_uint4(0, 0, 0, 0);
        float wa = 0.f, wb = 0.f;
        if (cnt > 0) {
            wa = __shfl_sync(0xffffffffu, p, 0);
            int s0 = __shfl_sync(0xffffffffu, s, 0);
            va = *(const uint4*)(g_xlh + (size_t)s0 * 128 + lane * 4);
        }
        if (cnt > 1) {
            wb = __shfl_sync(0xffffffffu, p, 1);
            int s1 = __shfl_sync(0xffffffffu, s, 1);
            vb = *(const uint4*)(g_xlh + (size_t)s1 * 128 + lane * 4);
        }
        for (int i = 0; i < cnt; i += 2) {
            uint4 v = va;
            float wv = wa;
            if (i + 2 < cnt) {
                wa = __shfl_sync(0xffffffffu, p, i + 2);
                int sn = __shfl_sync(0xffffffffu, s, i + 2);
                va = *(const uint4*)(g_xlh + (size_t)sn * 128 + lane * 4);
            }
            {
                const __half2* h2 = (const __half2*)&v;
                float2 f0 = __half22float2(h2[0]), f1 = __half22float2(h2[1]);
                float2 f2 = __half22float2(h2[2]), f3 = __half22float2(h2[3]);
                acc[0] += wv * f0.x; acc[1] += wv * f0.y;
                acc[2] += wv * f1.x; acc[3] += wv * f1.y;
                acc[4] += wv * f2.x; acc[5] += wv * f2.y;
                acc[6] += wv * f3.x; acc[7] += wv * f3.y;
            }
            if (i + 1 < cnt) {
                uint4 v2 = vb;
                float w2 = wb;
                if (i + 3 < cnt) {
                    wb = __shfl_sync(0xffffffffu, p, i + 3);
                    int sn = __shfl_sync(0xffffffffu, s, i + 3);
                    vb = *(const uint4*)(g_xlh + (size_t)sn * 128 + lane * 4);
                }
                const __half2* h2 = (const __half2*)&v2;
                float2 f0 = __half22float2(h2[0]), f1 = __half22float2(h2[1]);
                float2 f2 = __half22float2(h2[2]), f3 = __half22float2(h2[3]);
                acc[0] += w2 * f0.x; acc[1] += w2 * f0.y;
                acc[2] += w2 * f1.x; acc[3] += w2 * f1.y;
                acc[4] += w2 * f2.x; acc[5] += w2 * f2.y;
                acc[6] += w2 * f3.x; acc[7] += w2 * f3.y;
            }
        }
    }
    {
        float wv = __expf(selfa - m);
        denom = warp_sum(denom) + wv;
        uint4 v = *(const uint4*)(g_xlh + (size_t)gw * 128 + lane * 4);
        const __half2* h2 = (const __half2*)&v;
        float2 f0 = __half22float2(h2[0]), f1 = __half22float2(h2[1]);
        float2 f2 = __half22float2(h2[2]), f3 = __half22float2(h2[3]);
        acc[0] += wv * f0.x; acc[1] += wv * f0.y;
        acc[2] += wv * f1.x; acc[3] += wv * f1.y;
        acc[4] += wv * f2.x; acc[5] += wv * f2.y;
        acc[6] += wv * f3.x; acc[7] += wv * f3.y;
    }
    float inv = 1.0f / denom;
    float* hrow = g_h + (size_t)gw * EMB + lane * 8;
    const float4* b4 = (const float4*)(bias + lane * 8);
    float4 b0 = b4[0], b1 = b4[1];
    float4 h0 = *(float4*)hrow, h1 = *(float4*)(hrow + 4);
    float r[8];
    r[0] = acc[0] * inv + b0.x; r[1] = acc[1] * inv + b0.y;
    r[2] = acc[2] * inv + b0.z; r[3] = acc[3] * inv + b0.w;
    r[4] = acc[4] * inv + b1.x; r[5] = acc[5] * inv + b1.y;
    r[6] = acc[6] * inv + b1.z; r[7] = acc[7] * inv + b1.w;
    if (do_relu) {
#pragma unroll
        for (int j = 0; j < 8; j++) r[j] = fmaxf(r[j], 0.f);
    }
    r[0] += h0.x; r[1] += h0.y; r[2] += h0.z; r[3] += h0.w;
    r[4] += h1.x; r[5] += h1.y; r[6] += h1.z; r[7] += h1.w;
    *(float4*)hrow = make_float4(r[0], r[1], r[2], r[3]);
    *(float4*)(hrow + 4) = make_float4(r[4], r[5], r[6], r[7]);
    __half2 o[4];
    o[0] = __floats2half2_rn(r[0], r[1]);
    o[1] = __floats2half2_rn(r[2], r[3]);
    o[2] = __floats2half2_rn(r[4], r[5]);
    o[3] = __floats2half2_rn(r[6], r[7]);
    *(uint4*)(g_h16 + (size_t)gw * EMB + lane * 8) = *(uint4*)o;
}

// pooling: s[n] = h[n].wv, atomic into graph buckets
__global__ void k_pool(const int* __restrict__ batch) {
    int gw = (blockIdx.x * blockDim.x + threadIdx.x) >> 5;
    int lane = threadIdx.x & 31;
    if (gw >= NN) return;
    const float4* row = (const float4*)(g_h + (size_t)gw * EMB);
    const float4* w4 = (const float4*)g_wv;
    float4 v0 = row[lane], v1 = row[lane + 32];
    float4 w0 = w4[lane], w1 = w4[lane + 32];
    float s = v0.x * w0.x + v0.y * w0.y + v0.z * w0.z + v0.w * w0.w +
              v1.x * w1.x + v1.y * w1.y + v1.z * w1.z + v1.w * w1.w;
    s = warp_sum(s);
    if (lane == 0) {
        int g = batch[gw];
        atomicAdd(&g_gsum[g], s);
        atomicAdd(&g_gcnt[g], 1.0f);
    }
}

__global__ void k_final(float* __restrict__ out) {
    int g = blockIdx.x * blockDim.x + threadIdx.x;
    if (g < GG) out[g] = g_gsum[g] / fmaxf(g_gcnt[g], 1.0f) + g_bconst;
}

// ---------------- launch -----------------------------------------------------
extern "C" void kernel_launch(void* const* d_in, const int* in_sizes, int n_in,
                              void* d_out, int out_size) {
    const int* x = (const int*)d_in[0];
    const int* edge_index = (const int*)d_in[1];
    const int* edge_attr = (const int*)d_in[2];
    const int* batch = (const int*)d_in[3];
    const float* atom_emb = (const float*)d_in[4];
    const float* bond_emb = (const float*)d_in[5];
    const float* W = (const float*)d_in[6];
    const float* att_src = (const float*)d_in[7];
    const float* att_dst = (const float*)d_in[8];
    const float* We = (const float*)d_in[9];
    const float* att_edge = (const float*)d_in[10];
    const float* bias = (const float*)d_in[11];
    const float* W1 = (const float*)d_in[12];
    const float* b1 = (const float*)d_in[13];
    const float* W2 = (const float*)d_in[14];
    const float* b2 = (const float*)d_in[15];
    float* out = (float*)d_out;

    const int* src = edge_index;
    const int* dst = edge_index + EE;

    const int eblocks = (EE + 255) / 256;
    const int nwarp_blocks = (NN + 7) / 8;

    k_init<<<(3 * NN + 255) / 256, 256>>>();
    k_wconv<<<dim3(8, 8, 3), dim3(32, 8)>>>(W, atom_emb);
    k_atom<<<NN, 256>>>(x);
    // layer-0 GEMM placed 4th so the ncu capture profiles it
    k_mma<<<dim3(NPAD / 128, EMB / 128), 256>>>(0, att_src, att_dst);
    k_hist<<<eblocks, 256>>>(dst);
    k_scan_red<<<SCB, 1024>>>();
    k_scan_top<<<1, 32>>>();
    k_scan_low<<<SCB, 1024>>>();
    k_scatter<<<eblocks, 256>>>(src, dst, edge_attr);
    k_prep<<<4, 256>>>(W1, b1, W2, b2, We, att_edge, bond_emb);

    for (int l = 0; l < 3; l++) {
        if (l > 0)
            k_mma<<<dim3(NPAD / 128, EMB / 128), 256>>>(l, att_src + l * EMB,
                                                        att_dst + l * EMB);
        k_att<<<nwarp_blocks, 256>>>(bias + l * EMB, (l < 2) ? 1 : 0, l);
    }

    k_pool<<<nwarp_blocks, 256>>>(batch);
    k_final<<<2, 256>>>(out);
}

// round 9
// speedup vs baseline: 2.1136x; 1.0125x over previous
#include <cuda_runtime.h>
#include <cuda_fp16.h>
#include <math.h>

// Problem constants (fixed shapes for GAT_76184129896720)
#define NN 30000
#define NPAD 30080           // 235 * 128
#define EE 480000
#define EMB 256
#define GG 512
#define NEG_SLOPE 0.2f
#define SCB 30
#define EBLOCKS 1875         // (EE+255)/256

// ---------------- device scratch (static; no allocations allowed) ----------
__device__ float   g_h[NPAD * EMB];    // node features (fp32, residual stream)
__device__ __half  g_h16[NPAD * EMB];  // fp16 shadow of h (GEMM A input)
__device__ __half  g_w16[3 * EMB * EMB]; // per-layer W, fp16, transposed [n][k]
__device__ __half  g_emb16[9 * 128 * EMB]; // fp16 atom embedding tables
__device__ __half2 g_xlh[NPAD * 128];  // h @ W[l] in fp16 (256 halves per row)
__device__ float   g_asL[3 * NN];      // per-layer xl.att_src (epilogue-fused)
__device__ float   g_adL[3 * NN];      // per-layer xl.att_dst
__device__ int     g_deg[NN];
__device__ int     g_rowptr[NN + 1];
__device__ int     g_cursor[NN];
__device__ int     g_csr_src[EE];
__device__ unsigned g_csr_ea[EE];      // packed bond attrs
__device__ int     g_bsum[SCB];
__device__ int     g_boff[SCB];
__device__ float   g_dtable[3 * 48];
__device__ float   g_wv[EMB];
__device__ float   g_bconst;
__device__ float   g_gsum[GG];
__device__ float   g_gcnt[GG];

// ---------------- helpers ---------------------------------------------------
__device__ __forceinline__ float warp_sum(float v) {
#pragma unroll
    for (int o = 16; o > 0; o >>= 1) v += __shfl_xor_sync(0xffffffffu, v, o);
    return v;
}
__device__ __forceinline__ int warp_sum_i(int v) {
#pragma unroll
    for (int o = 16; o > 0; o >>= 1) v += __shfl_xor_sync(0xffffffffu, v, o);
    return v;
}
__device__ __forceinline__ void cp16(unsigned dst, const void* src) {
    asm volatile("cp.async.cg.shared.global [%0], [%1], 16;" :: "r"(dst), "l"(src));
}
__device__ __forceinline__ void ldsm4(unsigned addr, unsigned& r0, unsigned& r1,
                                      unsigned& r2, unsigned& r3) {
    asm volatile("ldmatrix.sync.aligned.m8n8.x4.shared.b16 {%0,%1,%2,%3}, [%4];"
                 : "=r"(r0), "=r"(r1), "=r"(r2), "=r"(r3) : "r"(addr));
}
// smem tile layout: 2 logical rows per 128B physical row, XOR swizzle.
__device__ __forceinline__ int swoff(int m, int kc) {
    int p = m >> 1;
    int c = ((m & 1) << 2) | (kc ^ (p & 3));
    return p * 128 + c * 16;
}

// ---------------- fused setup: init (blocks 0..351) + wconv (352..543) + prep
#define INIT_BLKS 352
#define WCONV_BLKS 192
__global__ void k_setup(const float* __restrict__ W, const float* __restrict__ emb,
                        const float* __restrict__ W1, const float* __restrict__ b1,
                        const float* __restrict__ W2, const float* __restrict__ b2,
                        const float* __restrict__ We, const float* __restrict__ att_edge,
                        const float* __restrict__ bond_emb) {
    int t = threadIdx.x;  // 256
    int bid = blockIdx.x;
    if (bid < INIT_BLKS) {
        int i = bid * 256 + t;
        if (i < NN) { g_deg[i] = 0; g_cursor[i] = 0; }
        if (i < GG) { g_gsum[i] = 0.f; g_gcnt[i] = 0.f; }
        if (i < (NPAD - NN) * EMB) {
            g_h[NN * EMB + i] = 0.f;
            g_h16[NN * EMB + i] = __float2half(0.f);
        }
        if (i < 3 * NN) { g_asL[i] = 0.f; g_adL[i] = 0.f; }
    } else if (bid < INIT_BLKS + WCONV_BLKS) {
        // weight convert+transpose + emb16 convert
        int wb = bid - INIT_BLKS;       // 0..191
        int l = wb >> 6;                // 0..2
        int rem = wb & 63;
        int kb = (rem & 7) * 32, nb = (rem >> 3) * 32;
        int tx = t & 31, ty = t >> 5;
        __shared__ float tile[32][33];
        for (int i = ty; i < 32; i += 8)
            tile[i][tx] = W[(size_t)l * EMB * EMB + (kb + i) * EMB + nb + tx];
        __syncthreads();
        for (int i = ty; i < 32; i += 8)
            g_w16[(size_t)l * EMB * EMB + (nb + i) * EMB + kb + tx] =
                __float2half(tile[tx][i]);
        int base = wb * 1536;  // 192*1536 = 294912 = 9*128*256
#pragma unroll
        for (int j = 0; j < 6; j++) {
            int idx = base + j * 256 + t;
            g_emb16[idx] = __float2half(emb[idx]);
        }
    } else if (bid == INIT_BLKS + WCONV_BLKS) {
        // head precompute
        int c = t;
        float acc = 0.f;
#pragma unroll 8
        for (int j = 0; j < EMB; j++) acc += W1[c * EMB + j] * W2[j];
        g_wv[c] = acc;
        __shared__ float sh[EMB];
        sh[c] = b1[c] * W2[c];
        __syncthreads();
        for (int s = 128; s > 0; s >>= 1) {
            if (c < s) sh[c] += sh[c + s];
            __syncthreads();
        }
        if (c == 0) g_bconst = sh[0] + b2[0];
    } else {
        // lprep for layer l
        int l = bid - (INIT_BLKS + WCONV_BLKS + 1);  // 0..2
        __shared__ float wa[3];
        int w = t >> 5, lane = t & 31;
        if (w < 3) {
            float p = 0.f;
            for (int k = lane; k < EMB; k += 32)
                p += We[(l * 3 + w) * EMB + k] * att_edge[l * EMB + k];
            p = warp_sum(p);
            if (lane == 0) wa[w] = p;
        }
        __syncthreads();
        if (t < 48) {
            int j = t >> 4, v = t & 15;
            const float* be = bond_emb + ((size_t)(l * 3 + j) * 16 + v) * 3;
            g_dtable[l * 48 + t] = be[0] * wa[0] + be[1] * wa[1] + be[2] * wa[2];
        }
    }
}

// fused AtomEncoder (blocks 0..29999) + degree histogram (blocks 30000..)
__global__ void k_atom_hist(const int* __restrict__ x, const int* __restrict__ dst) {
    int t = threadIdx.x;  // 256
    int bid = blockIdx.x;
    if (bid < NN) {
        __shared__ int xi[9];
        if (t < 9) xi[t] = x[bid * 9 + t];
        __syncthreads();
        float s = 0.f;
#pragma unroll
        for (int i = 0; i < 9; i++)
            s += __half2float(g_emb16[(i * 128 + xi[i]) * EMB + t]);
        g_h[bid * EMB + t] = s;
        g_h16[bid * EMB + t] = __float2half(s);
    } else {
        int e = (bid - NN) * 256 + t;
        if (e < EE) atomicAdd(&g_deg[dst[e]], 1);
    }
}

// --------- 3-phase multi-block exclusive scan of g_deg -> g_rowptr ----------
__global__ void k_scan_red() {
    __shared__ int ws[32];
    int t = threadIdx.x, lane = t & 31, wid = t >> 5;
    int idx = blockIdx.x * 1024 + t;
    int v = (idx < NN) ? g_deg[idx] : 0;
    v = warp_sum_i(v);
    if (lane == 0) ws[wid] = v;
    __syncthreads();
    if (wid == 0) {
        int s = ws[lane];
        s = warp_sum_i(s);
        if (lane == 0) g_bsum[blockIdx.x] = s;
    }
}
__global__ void k_scan_top() {
    int lane = threadIdx.x;
    int v = (lane < SCB) ? g_bsum[lane] : 0;
    int x = v;
#pragma unroll
    for (int o = 1; o < 32; o <<= 1) {
        int y = __shfl_up_sync(0xffffffffu, x, o);
        if (lane >= o) x += y;
    }
    if (lane < SCB) g_boff[lane] = x - v;
}
__global__ void k_scan_low() {
    __shared__ int ws[32];
    int t = threadIdx.x, lane = t & 31, wid = t >> 5;
    int idx = blockIdx.x * 1024 + t;
    int v = (idx < NN) ? g_deg[idx] : 0;
    int x = v;
#pragma unroll
    for (int o = 1; o < 32; o <<= 1) {
        int y = __shfl_up_sync(0xffffffffu, x, o);
        if (lane >= o) x += y;
    }
    if (lane == 31) ws[wid] = x;
    __syncthreads();
    if (wid == 0) {
        int w = ws[lane];
#pragma unroll
        for (int o = 1; o < 32; o <<= 1) {
            int y = __shfl_up_sync(0xffffffffu, w, o);
            if (lane >= o) w += y;
        }
        ws[lane] = w;
    }
    __syncthreads();
    int incl = x + ((wid > 0) ? ws[wid - 1] : 0) + g_boff[blockIdx.x];
    if (idx < NN) g_rowptr[idx + 1] = incl;
    if (idx == 0) g_rowptr[0] = 0;
}

__global__ void k_scatter(const int* __restrict__ src, const int* __restrict__ dst,
                          const int* __restrict__ ea) {
    int e = blockIdx.x * blockDim.x + threadIdx.x;
    if (e >= EE) return;
    int d = dst[e];
    int pos = g_rowptr[d] + atomicAdd(&g_cursor[d], 1);
    g_csr_src[pos] = src[e];
    g_csr_ea[pos] = (unsigned)ea[e * 3 + 0] | ((unsigned)ea[e * 3 + 1] << 8) |
                    ((unsigned)ea[e * 3 + 2] << 16);
}

// ------- fp16 GEMM + fused as/ad epilogue -----------------------------------
__global__ __launch_bounds__(256, 2) void k_mma(int l, const float* __restrict__ att_s,
                                                const float* __restrict__ att_d) {
    __shared__ __align__(16) char sm[49152];
    const unsigned smb = (unsigned)__cvta_generic_to_shared(sm);
    const int tid = threadIdx.x;
    const int lane = tid & 31;
    const int w = tid >> 5;
    const int tig = lane & 3, gid = lane >> 2;
    const int warp_m = w >> 2, warp_n = w & 3;
    const int r0 = blockIdx.x * 128, c0 = blockIdx.y * 128;

    const int lm = tid & 127;
    const int lkc = (tid >> 7) * 2;
    const __half* Ag = g_h16 + (size_t)(r0 + lm) * EMB + lkc * 8;
    const __half* Bg = g_w16 + (size_t)l * EMB * EMB + (size_t)(c0 + lm) * EMB + lkc * 8;
    const int sA0 = swoff(lm, lkc), sA1 = swoff(lm, lkc + 1);

    float acc[16][4];
#pragma unroll
    for (int i = 0; i < 16; i++)
#pragma unroll
        for (int j = 0; j < 4; j++) acc[i][j] = 0.f;

#define ISSUE(s)                                                          \
    {                                                                     \
        unsigned st = smb + ((s) % 3) * 16384;                            \
        cp16(st + sA0, Ag + (s) * 32);                                    \
        cp16(st + sA1, Ag + (s) * 32 + 8);                                \
        cp16(st + 8192 + sA0, Bg + (s) * 32);                             \
        cp16(st + 8192 + sA1, Bg + (s) * 32 + 8);                         \
        asm volatile("cp.async.commit_group;");                           \
    }

    ISSUE(0);
    ISSUE(1);

#pragma unroll
    for (int s = 0; s < 8; s++) {
        if (s < 7) asm volatile("cp.async.wait_group 1;");
        else       asm volatile("cp.async.wait_group 0;");
        __syncthreads();
        if (s + 2 < 8) ISSUE(s + 2);
        unsigned Ab = smb + (s % 3) * 16384;
        unsigned Bb = Ab + 8192;
#pragma unroll
        for (int kk = 0; kk < 32; kk += 16) {
            unsigned af[4][4], bf[4][2];
#pragma unroll
            for (int mt = 0; mt < 4; mt++) {
                int r = warp_m * 64 + mt * 16 + (lane & 15);
                int kc = (kk >> 3) + (lane >> 4);
                ldsm4(Ab + swoff(r, kc), af[mt][0], af[mt][1], af[mt][2], af[mt][3]);
            }
#pragma unroll
            for (int pr = 0; pr < 2; pr++) {
                int n = warp_n * 32 + pr * 16 + ((lane >> 4) & 1) * 8 + (lane & 7);
                int kc = (kk >> 3) + ((lane >> 3) & 1);
                ldsm4(Bb + swoff(n, kc), bf[2 * pr][0], bf[2 * pr][1],
                      bf[2 * pr + 1][0], bf[2 * pr + 1][1]);
            }
#pragma unroll
            for (int mt = 0; mt < 4; mt++)
#pragma unroll
                for (int nt = 0; nt < 4; nt++) {
                    float* c = acc[mt * 4 + nt];
                    asm volatile(
                        "mma.sync.aligned.m16n8k16.row.col.f32.f16.f16.f32 "
                        "{%0,%1,%2,%3}, {%4,%5,%6,%7}, {%8,%9}, {%0,%1,%2,%3};"
                        : "+f"(c[0]), "+f"(c[1]), "+f"(c[2]), "+f"(c[3])
                        : "r"(af[mt][0]), "r"(af[mt][1]), "r"(af[mt][2]), "r"(af[mt][3]),
                          "r"(bf[nt][0]), "r"(bf[nt][1]));
                }
        }
    }
#undef ISSUE
    float* asbuf = g_asL + l * NN;
    float* adbuf = g_adL + l * NN;
#pragma unroll
    for (int mt = 0; mt < 4; mt++) {
        int r = r0 + warp_m * 64 + mt * 16 + gid;
        float ps = 0.f, pd = 0.f, qs = 0.f, qd = 0.f;
#pragma unroll
        for (int nt = 0; nt < 4; nt++) {
            int c = c0 + warp_n * 32 + nt * 8 + 2 * tig;
            int ch = c >> 1;
            const float* a = acc[mt * 4 + nt];
            g_xlh[(size_t)r * 128 + ch] = __floats2half2_rn(a[0], a[1]);
            g_xlh[(size_t)(r + 8) * 128 + ch] = __floats2half2_rn(a[2], a[3]);
            float s0 = att_s[c], s1 = att_s[c + 1];
            float d0 = att_d[c], d1 = att_d[c + 1];
            ps += a[0] * s0 + a[1] * s1;
            pd += a[0] * d0 + a[1] * d1;
            qs += a[2] * s0 + a[3] * s1;
            qd += a[2] * d0 + a[3] * d1;
        }
#pragma unroll
        for (int o = 1; o <= 2; o <<= 1) {
            ps += __shfl_xor_sync(0xffffffffu, ps, o);
            pd += __shfl_xor_sync(0xffffffffu, pd, o);
            qs += __shfl_xor_sync(0xffffffffu, qs, o);
            qd += __shfl_xor_sync(0xffffffffu, qd, o);
        }
        if (tig == 0) {
            if (r < NN) { atomicAdd(asbuf + r, ps); atomicAdd(adbuf + r, pd); }
            if (r + 8 < NN) { atomicAdd(asbuf + r + 8, qs); atomicAdd(adbuf + r + 8, qd); }
        }
    }
}

// fused attention, SINGLE PASS (no max subtraction: |alpha| << 88, exp safe):
// p = exp(alpha); accumulate denom, esum, weighted rows; self-loop after.
__global__ void k_att(const float* __restrict__ bias, int do_relu, int l) {
    int gw = (blockIdx.x * blockDim.x + threadIdx.x) >> 5;
    int lane = threadIdx.x & 31;
    if (gw >= NN) return;
    const float* dt = g_dtable + l * 48;
    const float* asv = g_asL + l * NN;
    const float* adv = g_adL + l * NN;
    int start = g_rowptr[gw], end = g_rowptr[gw + 1];
    float adn = adv[gw];

    float acc[8] = {0, 0, 0, 0, 0, 0, 0, 0};
    float denom = 0.f, esum = 0.f;
    for (int cb = start; cb < end; cb += 32) {
        int pos = cb + lane;
        float p = 0.f;
        int s = 0;
        if (pos < end) {
            unsigned ea = g_csr_ea[pos];
            float ed = dt[ea & 15] + dt[16 + ((ea >> 8) & 15)] + dt[32 + ((ea >> 16) & 15)];
            s = g_csr_src[pos];
            float a = asv[s] + adn + ed;
            a = (a >= 0.f) ? a : NEG_SLOPE * a;
            p = __expf(a);
            esum += ed;
        }
        denom += p;
        int cnt = min(32, end - cb);
        uint4 va = make_uint4(0, 0, 0, 0), vb = make_uint4(0, 0, 0, 0);
        float wa = 0.f, wb = 0.f;
        if (cnt > 0) {
            wa = __shfl_sync(0xffffffffu, p, 0);
            int s0 = __shfl_sync(0xffffffffu, s, 0);
            va = *(const uint4*)(g_xlh + (size_t)s0 * 128 + lane * 4);
        }
        if (cnt > 1) {
            wb = __shfl_sync(0xffffffffu, p, 1);
            int s1 = __shfl_sync(0xffffffffu, s, 1);
            vb = *(const uint4*)(g_xlh + (size_t)s1 * 128 + lane * 4);
        }
        for (int i = 0; i < cnt; i += 2) {
            uint4 v = va;
            float wv = wa;
            if (i + 2 < cnt) {
                wa = __shfl_sync(0xffffffffu, p, i + 2);
                int sn = __shfl_sync(0xffffffffu, s, i + 2);
                va = *(const uint4*)(g_xlh + (size_t)sn * 128 + lane * 4);
            }
            {
                const __half2* h2 = (const __half2*)&v;
                float2 f0 = __half22float2(h2[0]), f1 = __half22float2(h2[1]);
                float2 f2 = __half22float2(h2[2]), f3 = __half22float2(h2[3]);
                acc[0] += wv * f0.x; acc[1] += wv * f0.y;
                acc[2] += wv * f1.x; acc[3] += wv * f1.y;
                acc[4] += wv * f2.x; acc[5] += wv * f2.y;
                acc[6] += wv * f3.x; acc[7] += wv * f3.y;
            }
            if (i + 1 < cnt) {
                uint4 v2 = vb;
                float w2 = wb;
                if (i + 3 < cnt) {
                    wb = __shfl_sync(0xffffffffu, p, i + 3);
                    int sn = __shfl_sync(0xffffffffu, s, i + 3);
                    vb = *(const uint4*)(g_xlh + (size_t)sn * 128 + lane * 4);
                }
                const __half2* h2 = (const __half2*)&v2;
                float2 f0 = __half22float2(h2[0]), f1 = __half22float2(h2[1]);
                float2 f2 = __half22float2(h2[2]), f3 = __half22float2(h2[3]);
                acc[0] += w2 * f0.x; acc[1] += w2 * f0.y;
                acc[2] += w2 * f1.x; acc[3] += w2 * f1.y;
                acc[4] += w2 * f2.x; acc[5] += w2 * f2.y;
                acc[6] += w2 * f3.x; acc[7] += w2 * f3.y;
            }
        }
    }
    // self loop (computed after esum known)
    {
        esum = warp_sum(esum);
        int deg = end - start;
        float selfa = asv[gw] + adn + esum / fmaxf((float)deg, 1.0f);
        selfa = (selfa >= 0.f) ? selfa : NEG_SLOPE * selfa;
        float wv = __expf(selfa);
        denom = warp_sum(denom) + wv;
        uint4 v = *(const uint4*)(g_xlh + (size_t)gw * 128 + lane * 4);
        const __half2* h2 = (const __half2*)&v;
        float2 f0 = __half22float2(h2[0]), f1 = __half22float2(h2[1]);
        float2 f2 = __half22float2(h2[2]), f3 = __half22float2(h2[3]);
        acc[0] += wv * f0.x; acc[1] += wv * f0.y;
        acc[2] += wv * f1.x; acc[3] += wv * f1.y;
        acc[4] += wv * f2.x; acc[5] += wv * f2.y;
        acc[6] += wv * f3.x; acc[7] += wv * f3.y;
    }
    float inv = 1.0f / denom;
    float* hrow = g_h + (size_t)gw * EMB + lane * 8;
    const float4* b4 = (const float4*)(bias + lane * 8);
    float4 b0 = b4[0], b1 = b4[1];
    float4 h0 = *(float4*)hrow, h1 = *(float4*)(hrow + 4);
    float r[8];
    r[0] = acc[0] * inv + b0.x; r[1] = acc[1] * inv + b0.y;
    r[2] = acc[2] * inv + b0.z; r[3] = acc[3] * inv + b0.w;
    r[4] = acc[4] * inv + b1.x; r[5] = acc[5] * inv + b1.y;
    r[6] = acc[6] * inv + b1.z; r[7] = acc[7] * inv + b1.w;
    if (do_relu) {
#pragma unroll
        for (int j = 0; j < 8; j++) r[j] = fmaxf(r[j], 0.f);
    }
    r[0] += h0.x; r[1] += h0.y; r[2] += h0.z; r[3] += h0.w;
    r[4] += h1.x; r[5] += h1.y; r[6] += h1.z; r[7] += h1.w;
    *(float4*)hrow = make_float4(r[0], r[1], r[2], r[3]);
    *(float4*)(hrow + 4) = make_float4(r[4], r[5], r[6], r[7]);
    __half2 o[4];
    o[0] = __floats2half2_rn(r[0], r[1]);
    o[1] = __floats2half2_rn(r[2], r[3]);
    o[2] = __floats2half2_rn(r[4], r[5]);
    o[3] = __floats2half2_rn(r[6], r[7]);
    *(uint4*)(g_h16 + (size_t)gw * EMB + lane * 8) = *(uint4*)o;
}

// pooling: s[n] = h[n].wv, atomic into graph buckets
__global__ void k_pool(const int* __restrict__ batch) {
    int gw = (blockIdx.x * blockDim.x + threadIdx.x) >> 5;
    int lane = threadIdx.x & 31;
    if (gw >= NN) return;
    const float4* row = (const float4*)(g_h + (size_t)gw * EMB);
    const float4* w4 = (const float4*)g_wv;
    float4 v0 = row[lane], v1 = row[lane + 32];
    float4 w0 = w4[lane], w1 = w4[lane + 32];
    float s = v0.x * w0.x + v0.y * w0.y + v0.z * w0.z + v0.w * w0.w +
              v1.x * w1.x + v1.y * w1.y + v1.z * w1.z + v1.w * w1.w;
    s = warp_sum(s);
    if (lane == 0) {
        int g = batch[gw];
        atomicAdd(&g_gsum[g], s);
        atomicAdd(&g_gcnt[g], 1.0f);
    }
}

__global__ void k_final(float* __restrict__ out) {
    int g = blockIdx.x * blockDim.x + threadIdx.x;
    if (g < GG) out[g] = g_gsum[g] / fmaxf(g_gcnt[g], 1.0f) + g_bconst;
}

// ---------------- launch -----------------------------------------------------
extern "C" void kernel_launch(void* const* d_in, const int* in_sizes, int n_in,
                              void* d_out, int out_size) {
    const int* x = (const int*)d_in[0];
    const int* edge_index = (const int*)d_in[1];
    const int* edge_attr = (const int*)d_in[2];
    const int* batch = (const int*)d_in[3];
    const float* atom_emb = (const float*)d_in[4];
    const float* bond_emb = (const float*)d_in[5];
    const float* W = (const float*)d_in[6];
    const float* att_src = (const float*)d_in[7];
    const float* att_dst = (const float*)d_in[8];
    const float* We = (const float*)d_in[9];
    const float* att_edge = (const float*)d_in[10];
    const float* bias = (const float*)d_in[11];
    const float* W1 = (const float*)d_in[12];
    const float* b1 = (const float*)d_in[13];
    const float* W2 = (const float*)d_in[14];
    const float* b2 = (const float*)d_in[15];
    float* out = (float*)d_out;

    const int* src = edge_index;
    const int* dst = edge_index + EE;

    const int nwarp_blocks = (NN + 7) / 8;

    // 1: fused init + weight/emb convert + head/lprep precompute
    k_setup<<<INIT_BLKS + WCONV_BLKS + 4, 256>>>(W, atom_emb, W1, b1, W2, b2,
                                                 We, att_edge, bond_emb);
    // 2: fused atom encoder + degree histogram
    k_atom_hist<<<NN + EBLOCKS, 256>>>(x, dst);
    // 3: scan reduce (needs hist)
    k_scan_red<<<SCB, 1024>>>();
    // 4: layer-0 GEMM (profiled launch)
    k_mma<<<dim3(NPAD / 128, EMB / 128), 256>>>(0, att_src, att_dst);
    k_scan_top<<<1, 32>>>();
    k_scan_low<<<SCB, 1024>>>();
    k_scatter<<<EBLOCKS, 256>>>(src, dst, edge_attr);

    for (int l = 0; l < 3; l++) {
        if (l > 0)
            k_mma<<<dim3(NPAD / 128, EMB / 128), 256>>>(l, att_src + l * EMB,
                                                        att_dst + l * EMB);
        k_att<<<nwarp_blocks, 256>>>(bias + l * EMB, (l < 2) ? 1 : 0, l);
    }

    k_pool<<<nwarp_blocks, 256>>>(batch);
    k_final<<<2, 256>>>(out);
}